// round 11
// baseline (speedup 1.0000x reference)
#include <cuda_runtime.h>
#include <cuda_fp16.h>
#include <math.h>
#include <stdint.h>

// Problem constants
#define T_FR 32
#define NN 512
#define FF 256
#define HH 8
#define LL 3
#define DIN 3
#define MAXN 128
#define SCH 32   // spmm column chunk

// ---------------- scratch (device globals; allocation-free rule) ----------------
__device__ float  g_x[T_FR * NN * FF];
__device__ float  g_Wh[T_FR * HH * NN * FF];
__device__ __half g_xh[T_FR * NN * FF];
__device__ __half g_xl[T_FR * NN * FF];
__device__ __half g_xch[T_FR * NN * HH * FF];
__device__ __half g_xcl[T_FR * NN * HH * FF];
__device__ __half g_Wth[LL * HH * FF * FF];     // W_heads^T [l][h][n][k] fp16
__device__ __half g_Woth[LL * FF * HH * FF];    // W_out^T   [l][n][k]    fp16
__device__ float  g_f[T_FR * HH * NN];
__device__ float  g_g[T_FR * HH * NN];
__device__ float  g_P[(long)T_FR * HH * NN * MAXN];
__device__ int    g_nnz[NN];
__device__ int    g_cols[NN * MAXN];

// ---------------- helpers ----------------
__device__ __forceinline__ void split_h(float x, __half& h, __half& l) {
    h = __float2half_rn(x);
    l = __float2half_rn(x - __half2float(h));
}
__device__ __forceinline__ uint32_t smem_u32(const void* p) {
    uint32_t a;
    asm("{ .reg .u64 t; cvta.to.shared.u64 t, %1; cvt.u32.u64 %0, t; }" : "=r"(a) : "l"(p));
    return a;
}
__device__ __forceinline__ void cp16(uint32_t dst, const void* src) {
    asm volatile("cp.async.cg.shared.global [%0], [%1], 16;" :: "r"(dst), "l"(src));
}
__device__ __forceinline__ void ldsm4(uint32_t* r, uint32_t addr) {
    asm volatile("ldmatrix.sync.aligned.m8n8.x4.shared.b16 {%0,%1,%2,%3}, [%4];"
        : "=r"(r[0]), "=r"(r[1]), "=r"(r[2]), "=r"(r[3]) : "r"(addr));
}
__device__ __forceinline__ void mma_fp16(float* c, const uint32_t* a, const uint32_t* b) {
    asm volatile("mma.sync.aligned.m16n8k16.row.col.f32.f16.f16.f32 "
        "{%0,%1,%2,%3}, {%4,%5,%6,%7}, {%8,%9}, {%0,%1,%2,%3};"
        : "+f"(c[0]), "+f"(c[1]), "+f"(c[2]), "+f"(c[3])
        : "r"(a[0]), "r"(a[1]), "r"(a[2]), "r"(a[3]), "r"(b[0]), "r"(b[1]));
}

// ---------------- input projection -> fp16 hi/lo ----------------
__global__ void input_proj_kernel(const float* __restrict__ pose,
                                  const float* __restrict__ Wp,
                                  const float* __restrict__ bp,
                                  __half* __restrict__ xh, __half* __restrict__ xl) {
    long idx = (long)blockIdx.x * blockDim.x + threadIdx.x;
    if (idx >= (long)T_FR * NN * FF) return;
    int f = (int)(idx % FF);
    long tn = idx / FF;
    const float* p = pose + tn * DIN;
    float v = p[0] * Wp[f] + p[1] * Wp[FF + f] + p[2] * Wp[2 * FF + f] + bp[f];
    __half h, l; split_h(v, h, l);
    xh[idx] = h; xl[idx] = l;
}

// ---------------- weight transpose: W [K][N] fp32 -> Wt [N][K] fp16 ----------------
__global__ void wsplit_kernel(const float* __restrict__ W,
                              __half* __restrict__ hi, int K, int N) {
    __shared__ float tile[32][33];
    int b = blockIdx.z;
    const float* Wb = W + (long)b * K * N;
    __half* hb = hi + (long)b * K * N;
    int kb = blockIdx.y * 32, nb = blockIdx.x * 32;
    for (int r = threadIdx.y; r < 32; r += 8)
        tile[r][threadIdx.x] = Wb[(long)(kb + r) * N + nb + threadIdx.x];
    __syncthreads();
    for (int r = threadIdx.y; r < 32; r += 8) {
        float v = tile[threadIdx.x][r];
        long o = (long)(nb + r) * K + kb + threadIdx.x;
        hb[o] = __float2half_rn(v);
    }
}

// ---------------- adjacency -> padded neighbor lists ----------------
__global__ void adjlist_kernel(const int* __restrict__ adj,
                               int* __restrict__ nnz, int* __restrict__ cols) {
    __shared__ int cnt;
    int i = blockIdx.x;
    if (threadIdx.x == 0) cnt = 0;
    __syncthreads();
    for (int j = threadIdx.x; j < NN; j += blockDim.x) {
        if (adj[(long)i * NN + j] > 0) {
            int p = atomicAdd(&cnt, 1);
            if (p < MAXN) cols[i * MAXN + p] = j;
        }
    }
    __syncthreads();
    if (threadIdx.x == 0) nnz[i] = (cnt < MAXN) ? cnt : MAXN;
}

// ---------------- zero f/g accumulators ----------------
__global__ void zero_fg_kernel(float* __restrict__ f, float* __restrict__ g, int n) {
    int i = blockIdx.x * blockDim.x + threadIdx.x;
    if (i < n) { f[i] = 0.f; g[i] = 0.f; }
}

// ============================================================================
// fp16 2-pass tensor-core GEMM: C = (Ahi + Alo) @ Bh^T, fused f/g epilogue.
// CTA tile 128x128, warp 32x64, BK=64, 2-stage cp.async, 1 sync / 64-K.
// smem stage (halfs, row stride 72): AHI 0, ALO 9216, BHI 18432; STG 27648.
// ============================================================================
#define RS  72
#define AHI 0
#define ALO (128 * RS)
#define BHI (2 * 128 * RS)
#define STG (3 * 128 * RS)
#define GEMM_SMEM (2 * STG * 2)   // 110592 bytes

__global__ __launch_bounds__(256)
void gemm_tc(const __half* __restrict__ Ah, const __half* __restrict__ Al,
             const __half* __restrict__ Bh,
             float* __restrict__ C,
             int K, int lda, int ldb, int ldc,
             long aStride, int aDiv, long bStride, int bMod,
             long cOuter, int cDiv, long cInner, int epi,
             float* __restrict__ fOut, float* __restrict__ gOut,
             const float* __restrict__ aVec, int aMod, int fgEnable) {
    extern __shared__ __align__(16) unsigned short smg[];
    uint32_t sb = smem_u32(smg);

    int tid = threadIdx.x;
    int lane = tid & 31;
    int warp = tid >> 5;
    int wm = warp >> 1;
    int wn = warp & 1;
    int g = lane >> 2;
    int q = lane & 3;

    int b = blockIdx.z;
    int col0 = blockIdx.x * 128;
    int row0 = blockIdx.y * 128;
    const __half* AhB = Ah + (long)(b / aDiv) * aStride;
    const __half* AlB = Al + (long)(b / aDiv) * aStride;
    const __half* BhB = Bh + (long)(b % bMod) * bStride;
    float* Cb = C + (long)(b / cDiv) * cOuter + (long)(b % cDiv) * cInner;

    float acc[2][8][4];
    #pragma unroll
    for (int i = 0; i < 2; i++)
        #pragma unroll
        for (int j = 0; j < 8; j++)
            #pragma unroll
            for (int k = 0; k < 4; k++) acc[i][j][k] = 0.f;

    int aRowA = (lane & 15);
    int kHalf = (lane >> 4) << 3;

    // copy: 1024 cp16-triples per stage, 4 per thread; row = idx>>3, seg = idx&7
    auto issue_stage = [&](int k0, int st) {
        uint32_t base = sb + (uint32_t)(st * STG * 2);
        #pragma unroll
        for (int it = 0; it < 4; it++) {
            int idx = tid + it * 256;
            int row = idx >> 3;
            int seg = idx & 7;
            uint32_t d = base + (uint32_t)((row * RS + seg * 8) * 2);
            cp16(d + AHI * 2, AhB + (long)(row0 + row) * lda + k0 + seg * 8);
            cp16(d + ALO * 2, AlB + (long)(row0 + row) * lda + k0 + seg * 8);
            cp16(d + BHI * 2, BhB + (long)(col0 + row) * ldb + k0 + seg * 8);
        }
        asm volatile("cp.async.commit_group;");
    };

    int nIter = K >> 6;
    issue_stage(0, 0);

    for (int i = 0; i < nIter; i++) {
        asm volatile("cp.async.wait_group 0;");
        __syncthreads();
        if (i + 1 < nIter) issue_stage((i + 1) << 6, (i + 1) & 1);

        uint32_t stBase = sb + (uint32_t)((i & 1) * STG * 2);
        #pragma unroll
        for (int kk = 0; kk < 64; kk += 16) {
            uint32_t ah[2][4], al[2][4], bf[8][2];
            #pragma unroll
            for (int mt = 0; mt < 2; mt++) {
                uint32_t addr = stBase + (uint32_t)(((AHI) + (wm * 32 + mt * 16 + aRowA) * RS + kk + kHalf) * 2);
                ldsm4(ah[mt], addr);
                ldsm4(al[mt], addr + (ALO - AHI) * 2);
            }
            #pragma unroll
            for (int ng = 0; ng < 4; ng++) {
                uint32_t r[4];
                uint32_t addr = stBase + (uint32_t)(((BHI) + (wn * 64 + ng * 16 + aRowA) * RS + kk + kHalf) * 2);
                ldsm4(r, addr);
                bf[ng * 2 + 0][0] = r[0]; bf[ng * 2 + 0][1] = r[2];
                bf[ng * 2 + 1][0] = r[1]; bf[ng * 2 + 1][1] = r[3];
            }
            #pragma unroll
            for (int mt = 0; mt < 2; mt++)
                #pragma unroll
                for (int nt = 0; nt < 8; nt++) mma_fp16(acc[mt][nt], ah[mt], bf[nt]);
            #pragma unroll
            for (int mt = 0; mt < 2; mt++)
                #pragma unroll
                for (int nt = 0; nt < 8; nt++) mma_fp16(acc[mt][nt], al[mt], bf[nt]);
        }
    }

    // ---- epilogue: store C (+epi), fused f/g partial dots ----
    float facc[4] = {0.f, 0.f, 0.f, 0.f};
    float gacc[4] = {0.f, 0.f, 0.f, 0.f};
    const float* av = fgEnable ? (aVec + (long)(b % aMod) * (2 * FF)) : (const float*)0;

    #pragma unroll
    for (int mt = 0; mt < 2; mt++) {
        #pragma unroll
        for (int nt = 0; nt < 8; nt++) {
            int r = row0 + wm * 32 + mt * 16 + g;
            int c = col0 + wn * 64 + nt * 8 + 2 * q;
            float v0 = acc[mt][nt][0], v1 = acc[mt][nt][1];
            float v2 = acc[mt][nt][2], v3 = acc[mt][nt][3];
            if (fgEnable) {
                float a10 = av[c], a11 = av[c + 1];
                float a20 = av[FF + c], a21 = av[FF + c + 1];
                facc[mt * 2 + 0] += v0 * a10 + v1 * a11;
                gacc[mt * 2 + 0] += v0 * a20 + v1 * a21;
                facc[mt * 2 + 1] += v2 * a10 + v3 * a11;
                gacc[mt * 2 + 1] += v2 * a20 + v3 * a21;
            }
            float vv[4] = {v0, v1, v2, v3};
            #pragma unroll
            for (int j = 0; j < 4; j++) {
                float u = vv[j];
                if (epi >= 1) u = (u >= 0.f) ? u : expm1f(u);
                if (epi == 2) u = (u >= 0.f) ? u : expm1f(u);
                vv[j] = u;
            }
            *(float2*)&Cb[(long)r * ldc + c] = make_float2(vv[0], vv[1]);
            *(float2*)&Cb[(long)(r + 8) * ldc + c] = make_float2(vv[2], vv[3]);
        }
    }
    if (fgEnable) {
        #pragma unroll
        for (int idx = 0; idx < 4; idx++) {
            facc[idx] += __shfl_xor_sync(0xffffffffu, facc[idx], 1);
            facc[idx] += __shfl_xor_sync(0xffffffffu, facc[idx], 2);
            gacc[idx] += __shfl_xor_sync(0xffffffffu, gacc[idx], 1);
            gacc[idx] += __shfl_xor_sync(0xffffffffu, gacc[idx], 2);
        }
        if (q == 0) {
            #pragma unroll
            for (int mt = 0; mt < 2; mt++) {
                #pragma unroll
                for (int s = 0; s < 2; s++) {
                    int row = row0 + wm * 32 + mt * 16 + g + s * 8;
                    long w = (long)b * NN + row;
                    atomicAdd(&fOut[w], facc[mt * 2 + s]);
                    atomicAdd(&gOut[w], gacc[mt * 2 + s]);
                }
            }
        }
    }
}

// ---------------- sparse softmax over neighbor lists ----------------
__global__ void softmax_sparse_kernel(const float* __restrict__ f, const float* __restrict__ g,
                                      const int* __restrict__ nnz, const int* __restrict__ cols,
                                      float* __restrict__ Pc, int totalRows) {
    int w = (int)(((long)blockIdx.x * blockDim.x + threadIdx.x) >> 5);
    int lane = threadIdx.x & 31;
    if (w >= totalRows) return;
    int b = w >> 9;
    int i = w & 511;
    float fi = f[w];
    const float* gb = g + (long)b * NN;
    int n = nnz[i];
    const int* crow = cols + i * MAXN;
    int nc = (n + 31) >> 5;

    float e[4];
    float mx = -INFINITY;
    for (int c = 0; c < nc; c++) {
        int k = c * 32 + lane;
        float v = -INFINITY;
        if (k < n) {
            float xv = fi + gb[crow[k]];
            v = (xv >= 0.f) ? xv : 0.2f * xv;
        }
        e[c] = v;
        mx = fmaxf(mx, v);
    }
    #pragma unroll
    for (int o = 16; o > 0; o >>= 1) mx = fmaxf(mx, __shfl_xor_sync(0xffffffffu, mx, o));

    float s = 0.f;
    for (int c = 0; c < nc; c++) {
        float ev = (e[c] > -1e30f) ? __expf(e[c] - mx) : 0.f;
        e[c] = ev; s += ev;
    }
    #pragma unroll
    for (int o = 16; o > 0; o >>= 1) s += __shfl_xor_sync(0xffffffffu, s, o);
    float inv = 1.0f / s;

    float* prow = Pc + (long)w * MAXN;
    for (int c = 0; c < nc; c++) {
        int k = c * 32 + lane;
        if (k < n) prow[k] = e[c] * inv;
    }
}

// ---------------- sparse attention apply; 32-col chunks, dual accumulators ----------------
__global__ __launch_bounds__(256)
void spmm_kernel(const float* __restrict__ Pc, const float* __restrict__ Wh,
                 const int* __restrict__ nnz, const int* __restrict__ cols,
                 __half* __restrict__ Chi, __half* __restrict__ Clo,
                 float* __restrict__ Cf, int writeF,
                 long whStride, long cOuter, int cDiv, long cInner, int ldc, int epi) {
    extern __shared__ float WhS[];     // [NN][SCH]
    int b = blockIdx.y;
    int c0 = blockIdx.x * SCH;
    const float* Whb = Wh + (long)b * whStride;
    long cOff = (long)(b / cDiv) * cOuter + (long)(b % cDiv) * cInner;

    for (int idx = threadIdx.x; idx < NN * (SCH / 4); idx += 256) {
        int row = idx >> 3;
        int col4 = (idx & 7) << 2;
        *(float4*)&WhS[row * SCH + col4] =
            *(const float4*)&Whb[(long)row * FF + c0 + col4];
    }
    __syncthreads();

    int warp = threadIdx.x >> 5;
    int lane = threadIdx.x & 31;
    for (int i = warp; i < NN; i += 8) {
        int n = nnz[i];
        const int* crow = cols + i * MAXN;
        const float* prow = Pc + ((long)b * NN + i) * MAXN;
        float a0 = 0.f, a1 = 0.f;
        int k = 0;
        for (; k + 2 <= n; k += 2) {
            int j0 = crow[k], j1 = crow[k + 1];
            float w0 = prow[k], w1 = prow[k + 1];
            a0 += w0 * WhS[j0 * SCH + lane];
            a1 += w1 * WhS[j1 * SCH + lane];
        }
        if (k < n) a0 += prow[k] * WhS[crow[k] * SCH + lane];
        float a = a0 + a1;
        if (epi >= 1) a = (a >= 0.f) ? a : expm1f(a);
        if (epi == 2) a = (a >= 0.f) ? a : expm1f(a);
        long o = cOff + (long)i * ldc + c0 + lane;
        __half h, l; split_h(a, h, l);
        Chi[o] = h; Clo[o] = l;
        if (writeF) Cf[o] = a;
    }
}

// ---------------- final pool ----------------
__global__ void pool_kernel(const float* __restrict__ x, const float* __restrict__ Wo,
                            const float* __restrict__ bo, float* __restrict__ out) {
    int t = blockIdx.x;
    int f = threadIdx.x;
    __shared__ float m[FF];
    const float* xt = x + (long)t * NN * FF;
    float s = 0.f;
    for (int n = 0; n < NN; n++) s += xt[n * FF + f];
    m[f] = s * (1.0f / NN);
    __syncthreads();
    float o = bo[f];
    for (int k = 0; k < FF; k++) o += m[k] * Wo[k * FF + f];
    out[t * FF + f] = o;
}

// ---------------- host orchestration ----------------
extern "C" void kernel_launch(void* const* d_in, const int* in_sizes, int n_in,
                              void* d_out, int out_size) {
    const float* pose    = (const float*)d_in[0];
    const int*   adj     = (const int*)  d_in[1];
    const float* Wp      = (const float*)d_in[2];
    const float* bp      = (const float*)d_in[3];
    const float* W_heads = (const float*)d_in[4];
    const float* a_heads = (const float*)d_in[5];
    const float* W_out   = (const float*)d_in[6];
    const float* a_out   = (const float*)d_in[7];
    const float* Wo      = (const float*)d_in[8];
    const float* bo      = (const float*)d_in[9];
    float* out = (float*)d_out;

    float *x, *Wh, *fb, *gb, *P;
    __half *xh, *xl, *xch, *xcl, *Wth, *Woth;
    int *nnz, *colsArr;
    cudaGetSymbolAddress((void**)&x,    g_x);
    cudaGetSymbolAddress((void**)&Wh,   g_Wh);
    cudaGetSymbolAddress((void**)&xh,   g_xh);
    cudaGetSymbolAddress((void**)&xl,   g_xl);
    cudaGetSymbolAddress((void**)&xch,  g_xch);
    cudaGetSymbolAddress((void**)&xcl,  g_xcl);
    cudaGetSymbolAddress((void**)&Wth,  g_Wth);
    cudaGetSymbolAddress((void**)&Woth, g_Woth);
    cudaGetSymbolAddress((void**)&fb,   g_f);
    cudaGetSymbolAddress((void**)&gb,   g_g);
    cudaGetSymbolAddress((void**)&P,    g_P);
    cudaGetSymbolAddress((void**)&nnz,  g_nnz);
    cudaGetSymbolAddress((void**)&colsArr, g_cols);

    static bool attrSet = false;
    if (!attrSet) {
        cudaFuncSetAttribute(spmm_kernel,
                             cudaFuncAttributeMaxDynamicSharedMemorySize, NN * SCH * 4);
        cudaFuncSetAttribute(gemm_tc,
                             cudaFuncAttributeMaxDynamicSharedMemorySize, GEMM_SMEM);
        attrSet = true;
    }

    adjlist_kernel<<<NN, 256>>>(adj, nnz, colsArr);

    {
        dim3 blk(32, 8);
        dim3 gh(FF / 32, FF / 32, LL * HH);
        wsplit_kernel<<<gh, blk>>>(W_heads, Wth, FF, FF);
        dim3 go(FF / 32, (HH * FF) / 32, LL);
        wsplit_kernel<<<go, blk>>>(W_out, Woth, HH * FF, FF);
    }

    {
        long total = (long)T_FR * NN * FF;
        input_proj_kernel<<<(unsigned)((total + 255) / 256), 256>>>(pose, Wp, bp, xh, xl);
    }

    for (int l = 0; l < LL; l++) {
        const __half* Wlh = Wth  + (long)l * HH * FF * FF;
        const __half* Woh = Woth + (long)l * FF * HH * FF;
        const float* al  = a_heads + (long)l * HH * 2 * FF;
        const float* aol = a_out   + (long)l * 2 * FF;

        // 2a. Wh = x @ W_heads  (BK=64 pipeline, fused f/g)
        zero_fg_kernel<<<(T_FR * HH * NN + 255) / 256, 256>>>(fb, gb, T_FR * HH * NN);
        {
            dim3 grid(FF / 128, NN / 128, T_FR * HH);
            gemm_tc<<<grid, 256, GEMM_SMEM>>>(xh, xl, Wlh, Wh,
                FF, FF, FF, FF,
                (long)NN * FF, HH,
                (long)FF * FF, HH,
                (long)NN * FF, 1, 0,
                0, fb, gb, al, HH, 1);
        }
        // 2c. sparse softmax -> compact P
        {
            int rows = T_FR * HH * NN;
            softmax_sparse_kernel<<<(rows * 32 + 255) / 256, 256>>>(fb, gb, nnz, colsArr, P, rows);
        }
        // 2d. xcat = elu(P @ Wh) -> fp16 hi/lo
        {
            dim3 grid(FF / SCH, T_FR * HH);
            spmm_kernel<<<grid, 256, NN * SCH * 4>>>(P, Wh, nnz, colsArr,
                xch, xcl, (float*)0, 0,
                (long)NN * FF,
                (long)NN * HH * FF, HH, FF, HH * FF, 1);
        }
        // 2e. Whout = xcat @ W_out  (BK=64, K=2048, fused f/g)
        zero_fg_kernel<<<(T_FR * NN + 255) / 256, 256>>>(fb, gb, T_FR * NN);
        {
            dim3 grid(FF / 128, NN / 128, T_FR);
            gemm_tc<<<grid, 256, GEMM_SMEM>>>(xch, xcl, Woh, Wh,
                HH * FF, HH * FF, HH * FF, FF,
                (long)NN * HH * FF, 1,
                0, 1,
                (long)NN * FF, 1, 0,
                0, fb, gb, aol, 1, 1);
        }
        // 2g. sparse softmax -> compact P
        {
            int rows = T_FR * NN;
            softmax_sparse_kernel<<<(rows * 32 + 255) / 256, 256>>>(fb, gb, nnz, colsArr, P, rows);
        }
        // 2h. x = elu(elu(P @ Whout)) -> fp16 hi/lo (+ fp32 last layer)
        {
            dim3 grid(FF / SCH, T_FR);
            spmm_kernel<<<grid, 256, NN * SCH * 4>>>(P, Wh, nnz, colsArr,
                xh, xl, x, (l == LL - 1) ? 1 : 0,
                (long)NN * FF,
                (long)NN * FF, 1, 0, FF, 2);
        }
    }

    pool_kernel<<<T_FR, 256>>>(x, Wo, bo, out);
}

// round 12
// speedup vs baseline: 1.0774x; 1.0774x over previous
#include <cuda_runtime.h>
#include <cuda_fp16.h>
#include <math.h>
#include <stdint.h>

// Problem constants
#define T_FR 32
#define NN 512
#define FF 256
#define HH 8
#define LL 3
#define DIN 3
#define MAXN 128
#define SCH 32   // spmm column chunk

// ---------------- scratch (device globals; allocation-free rule) ----------------
__device__ float  g_x[T_FR * NN * FF];
__device__ float  g_Wh[T_FR * HH * NN * FF];
__device__ __half g_xh[T_FR * NN * FF];
__device__ __half g_xl[T_FR * NN * FF];
__device__ __half g_xch[T_FR * NN * HH * FF];
__device__ __half g_xcl[T_FR * NN * HH * FF];
__device__ __half g_Wth[LL * HH * FF * FF];     // W_heads^T [l][h][n][k] fp16
__device__ __half g_Woth[LL * FF * HH * FF];    // W_out^T   [l][n][k]    fp16
__device__ float  g_f[T_FR * HH * NN];
__device__ float  g_g[T_FR * HH * NN];
__device__ float  g_P[(long)T_FR * HH * NN * MAXN];
__device__ int    g_nnz[NN];
__device__ int    g_cols[NN * MAXN];

// ---------------- helpers ----------------
__device__ __forceinline__ void split_h(float x, __half& h, __half& l) {
    h = __float2half_rn(x);
    l = __float2half_rn(x - __half2float(h));
}
__device__ __forceinline__ uint32_t smem_u32(const void* p) {
    uint32_t a;
    asm("{ .reg .u64 t; cvta.to.shared.u64 t, %1; cvt.u32.u64 %0, t; }" : "=r"(a) : "l"(p));
    return a;
}
__device__ __forceinline__ void cp16(uint32_t dst, const void* src) {
    asm volatile("cp.async.cg.shared.global [%0], [%1], 16;" :: "r"(dst), "l"(src));
}
__device__ __forceinline__ void ldsm4(uint32_t* r, uint32_t addr) {
    asm volatile("ldmatrix.sync.aligned.m8n8.x4.shared.b16 {%0,%1,%2,%3}, [%4];"
        : "=r"(r[0]), "=r"(r[1]), "=r"(r[2]), "=r"(r[3]) : "r"(addr));
}
__device__ __forceinline__ void mma_fp16(float* c, const uint32_t* a, const uint32_t* b) {
    asm volatile("mma.sync.aligned.m16n8k16.row.col.f32.f16.f16.f32 "
        "{%0,%1,%2,%3}, {%4,%5,%6,%7}, {%8,%9}, {%0,%1,%2,%3};"
        : "+f"(c[0]), "+f"(c[1]), "+f"(c[2]), "+f"(c[3])
        : "r"(a[0]), "r"(a[1]), "r"(a[2]), "r"(a[3]), "r"(b[0]), "r"(b[1]));
}

// ---------------- input projection -> fp16 hi/lo ----------------
__global__ void input_proj_kernel(const float* __restrict__ pose,
                                  const float* __restrict__ Wp,
                                  const float* __restrict__ bp,
                                  __half* __restrict__ xh, __half* __restrict__ xl) {
    long idx = (long)blockIdx.x * blockDim.x + threadIdx.x;
    if (idx >= (long)T_FR * NN * FF) return;
    int f = (int)(idx % FF);
    long tn = idx / FF;
    const float* p = pose + tn * DIN;
    float v = p[0] * Wp[f] + p[1] * Wp[FF + f] + p[2] * Wp[2 * FF + f] + bp[f];
    __half h, l; split_h(v, h, l);
    xh[idx] = h; xl[idx] = l;
}

// ---------------- weight transpose: W [K][N] fp32 -> Wt [N][K] fp16 ----------------
__global__ void wsplit_kernel(const float* __restrict__ W,
                              __half* __restrict__ hi, int K, int N) {
    __shared__ float tile[32][33];
    int b = blockIdx.z;
    const float* Wb = W + (long)b * K * N;
    __half* hb = hi + (long)b * K * N;
    int kb = blockIdx.y * 32, nb = blockIdx.x * 32;
    for (int r = threadIdx.y; r < 32; r += 8)
        tile[r][threadIdx.x] = Wb[(long)(kb + r) * N + nb + threadIdx.x];
    __syncthreads();
    for (int r = threadIdx.y; r < 32; r += 8) {
        float v = tile[threadIdx.x][r];
        long o = (long)(nb + r) * K + kb + threadIdx.x;
        hb[o] = __float2half_rn(v);
    }
}

// ---------------- adjacency -> padded neighbor lists ----------------
__global__ void adjlist_kernel(const int* __restrict__ adj,
                               int* __restrict__ nnz, int* __restrict__ cols) {
    __shared__ int cnt;
    int i = blockIdx.x;
    if (threadIdx.x == 0) cnt = 0;
    __syncthreads();
    for (int j = threadIdx.x; j < NN; j += blockDim.x) {
        if (adj[(long)i * NN + j] > 0) {
            int p = atomicAdd(&cnt, 1);
            if (p < MAXN) cols[i * MAXN + p] = j;
        }
    }
    __syncthreads();
    if (threadIdx.x == 0) nnz[i] = (cnt < MAXN) ? cnt : MAXN;
}

// ---------------- zero f/g accumulators ----------------
__global__ void zero_fg_kernel(float* __restrict__ f, float* __restrict__ g, int n) {
    int i = blockIdx.x * blockDim.x + threadIdx.x;
    if (i < n) { f[i] = 0.f; g[i] = 0.f; }
}

// ============================================================================
// fp16 2-pass tensor-core GEMM: C = (Ahi + Alo) @ Bh^T, fused f/g epilogue.
// CTA tile 128x128, warp tile 64x32 (8 warps = 2M x 4N), BK=32,
// 3-stage cp.async pipeline, 1 sync/iter (round-9 proven skeleton).
// ============================================================================
#define AHI 0
#define ALO 5120
#define BHI 10240
#define STG 15360
#define GEMM_SMEM (3 * STG * 2)   // 92160 bytes

__global__ __launch_bounds__(256)
void gemm_tc(const __half* __restrict__ Ah, const __half* __restrict__ Al,
             const __half* __restrict__ Bh,
             float* __restrict__ C,
             int K, int lda, int ldb, int ldc,
             long aStride, int aDiv, long bStride, int bMod,
             long cOuter, int cDiv, long cInner, int epi,
             float* __restrict__ fOut, float* __restrict__ gOut,
             const float* __restrict__ aVec, int aMod, int fgEnable) {
    extern __shared__ __align__(16) unsigned short smg[];
    uint32_t sb = smem_u32(smg);

    int tid = threadIdx.x;
    int lane = tid & 31;
    int warp = tid >> 5;
    int wm = warp >> 2;        // 0..1 -> rows wm*64
    int wn = warp & 3;         // 0..3 -> cols wn*32
    int g = lane >> 2;
    int q = lane & 3;

    int b = blockIdx.z;
    int col0 = blockIdx.x * 128;
    int row0 = blockIdx.y * 128;
    const __half* AhB = Ah + (long)(b / aDiv) * aStride;
    const __half* AlB = Al + (long)(b / aDiv) * aStride;
    const __half* BhB = Bh + (long)(b % bMod) * bStride;
    float* Cb = C + (long)(b / cDiv) * cOuter + (long)(b % cDiv) * cInner;

    float acc[4][4][4];
    #pragma unroll
    for (int i = 0; i < 4; i++)
        #pragma unroll
        for (int j = 0; j < 4; j++)
            #pragma unroll
            for (int k = 0; k < 4; k++) acc[i][j][k] = 0.f;

    int arow0 = tid >> 2, aseg = tid & 3;
    int aRowA = (lane & 15);
    int kHalf = (lane >> 4) << 3;

    auto issue_stage = [&](int k0, int st) {
        uint32_t base = sb + (uint32_t)(st * STG * 2);
        #pragma unroll
        for (int h = 0; h < 2; h++) {
            int row = arow0 + h * 64;
            uint32_t d = base + (uint32_t)((row * 40 + aseg * 8) * 2);
            cp16(d + AHI * 2, AhB + (long)(row0 + row) * lda + k0 + aseg * 8);
            cp16(d + ALO * 2, AlB + (long)(row0 + row) * lda + k0 + aseg * 8);
            cp16(d + BHI * 2, BhB + (long)(col0 + row) * ldb + k0 + aseg * 8);
        }
        asm volatile("cp.async.commit_group;");
    };

    int nIter = K >> 5;
    issue_stage(0, 0);
    issue_stage(32, 1);

    int slot = 0;
    for (int i = 0; i < nIter; i++) {
        if (i < nIter - 1) {
            asm volatile("cp.async.wait_group 1;");
        } else {
            asm volatile("cp.async.wait_group 0;");
        }
        __syncthreads();
        if (i + 2 < nIter) {
            int ws = slot + 2; if (ws >= 3) ws -= 3;
            issue_stage((i + 2) << 5, ws);
        }

        uint32_t stBase = sb + (uint32_t)(slot * STG * 2);
        #pragma unroll
        for (int kk = 0; kk < 32; kk += 16) {
            uint32_t ah[4][4], al[4][4], bf[4][2];
            #pragma unroll
            for (int mt = 0; mt < 4; mt++) {
                uint32_t addr = stBase + (uint32_t)(((AHI) + (wm * 64 + mt * 16 + aRowA) * 40 + kk + kHalf) * 2);
                ldsm4(ah[mt], addr);
                ldsm4(al[mt], addr + (ALO - AHI) * 2);
            }
            #pragma unroll
            for (int ng = 0; ng < 2; ng++) {
                uint32_t r[4];
                uint32_t addr = stBase + (uint32_t)(((BHI) + (wn * 32 + ng * 16 + aRowA) * 40 + kk + kHalf) * 2);
                ldsm4(r, addr);
                bf[ng * 2 + 0][0] = r[0]; bf[ng * 2 + 0][1] = r[2];
                bf[ng * 2 + 1][0] = r[1]; bf[ng * 2 + 1][1] = r[3];
            }
            #pragma unroll
            for (int mt = 0; mt < 4; mt++)
                #pragma unroll
                for (int nt = 0; nt < 4; nt++) mma_fp16(acc[mt][nt], ah[mt], bf[nt]);
            #pragma unroll
            for (int mt = 0; mt < 4; mt++)
                #pragma unroll
                for (int nt = 0; nt < 4; nt++) mma_fp16(acc[mt][nt], al[mt], bf[nt]);
        }
        slot++; if (slot >= 3) slot = 0;
    }

    // ---- epilogue: store C (+epi), fused f/g partial dots ----
    float facc[8] = {0.f, 0.f, 0.f, 0.f, 0.f, 0.f, 0.f, 0.f};
    float gacc[8] = {0.f, 0.f, 0.f, 0.f, 0.f, 0.f, 0.f, 0.f};
    const float* av = fgEnable ? (aVec + (long)(b % aMod) * (2 * FF)) : (const float*)0;

    #pragma unroll
    for (int mt = 0; mt < 4; mt++) {
        #pragma unroll
        for (int nt = 0; nt < 4; nt++) {
            int r = row0 + wm * 64 + mt * 16 + g;
            int c = col0 + wn * 32 + nt * 8 + 2 * q;
            float v0 = acc[mt][nt][0], v1 = acc[mt][nt][1];
            float v2 = acc[mt][nt][2], v3 = acc[mt][nt][3];
            if (fgEnable) {
                float a10 = av[c], a11 = av[c + 1];
                float a20 = av[FF + c], a21 = av[FF + c + 1];
                facc[mt * 2 + 0] += v0 * a10 + v1 * a11;
                gacc[mt * 2 + 0] += v0 * a20 + v1 * a21;
                facc[mt * 2 + 1] += v2 * a10 + v3 * a11;
                gacc[mt * 2 + 1] += v2 * a20 + v3 * a21;
            }
            float vv[4] = {v0, v1, v2, v3};
            #pragma unroll
            for (int j = 0; j < 4; j++) {
                float u = vv[j];
                if (epi >= 1) u = (u >= 0.f) ? u : expm1f(u);
                if (epi == 2) u = (u >= 0.f) ? u : expm1f(u);
                vv[j] = u;
            }
            *(float2*)&Cb[(long)r * ldc + c] = make_float2(vv[0], vv[1]);
            *(float2*)&Cb[(long)(r + 8) * ldc + c] = make_float2(vv[2], vv[3]);
        }
    }
    if (fgEnable) {
        #pragma unroll
        for (int idx = 0; idx < 8; idx++) {
            facc[idx] += __shfl_xor_sync(0xffffffffu, facc[idx], 1);
            facc[idx] += __shfl_xor_sync(0xffffffffu, facc[idx], 2);
            gacc[idx] += __shfl_xor_sync(0xffffffffu, gacc[idx], 1);
            gacc[idx] += __shfl_xor_sync(0xffffffffu, gacc[idx], 2);
        }
        if (q == 0) {
            #pragma unroll
            for (int mt = 0; mt < 4; mt++) {
                #pragma unroll
                for (int s = 0; s < 2; s++) {
                    int row = row0 + wm * 64 + mt * 16 + g + s * 8;
                    long w = (long)b * NN + row;
                    atomicAdd(&fOut[w], facc[mt * 2 + s]);
                    atomicAdd(&gOut[w], gacc[mt * 2 + s]);
                }
            }
        }
    }
}

// ---------------- sparse softmax over neighbor lists ----------------
__global__ void softmax_sparse_kernel(const float* __restrict__ f, const float* __restrict__ g,
                                      const int* __restrict__ nnz, const int* __restrict__ cols,
                                      float* __restrict__ Pc, int totalRows) {
    int w = (int)(((long)blockIdx.x * blockDim.x + threadIdx.x) >> 5);
    int lane = threadIdx.x & 31;
    if (w >= totalRows) return;
    int b = w >> 9;
    int i = w & 511;
    float fi = f[w];
    const float* gb = g + (long)b * NN;
    int n = nnz[i];
    const int* crow = cols + i * MAXN;
    int nc = (n + 31) >> 5;

    float e[4];
    float mx = -INFINITY;
    for (int c = 0; c < nc; c++) {
        int k = c * 32 + lane;
        float v = -INFINITY;
        if (k < n) {
            float xv = fi + gb[crow[k]];
            v = (xv >= 0.f) ? xv : 0.2f * xv;
        }
        e[c] = v;
        mx = fmaxf(mx, v);
    }
    #pragma unroll
    for (int o = 16; o > 0; o >>= 1) mx = fmaxf(mx, __shfl_xor_sync(0xffffffffu, mx, o));

    float s = 0.f;
    for (int c = 0; c < nc; c++) {
        float ev = (e[c] > -1e30f) ? __expf(e[c] - mx) : 0.f;
        e[c] = ev; s += ev;
    }
    #pragma unroll
    for (int o = 16; o > 0; o >>= 1) s += __shfl_xor_sync(0xffffffffu, s, o);
    float inv = 1.0f / s;

    float* prow = Pc + (long)w * MAXN;
    for (int c = 0; c < nc; c++) {
        int k = c * 32 + lane;
        if (k < n) prow[k] = e[c] * inv;
    }
}

// ---------------- sparse attention apply; 32-col chunks, dual accumulators ----------------
__global__ __launch_bounds__(256)
void spmm_kernel(const float* __restrict__ Pc, const float* __restrict__ Wh,
                 const int* __restrict__ nnz, const int* __restrict__ cols,
                 __half* __restrict__ Chi, __half* __restrict__ Clo,
                 float* __restrict__ Cf, int writeF,
                 long whStride, long cOuter, int cDiv, long cInner, int ldc, int epi) {
    extern __shared__ float WhS[];     // [NN][SCH]
    int b = blockIdx.y;
    int c0 = blockIdx.x * SCH;
    const float* Whb = Wh + (long)b * whStride;
    long cOff = (long)(b / cDiv) * cOuter + (long)(b % cDiv) * cInner;

    for (int idx = threadIdx.x; idx < NN * (SCH / 4); idx += 256) {
        int row = idx >> 3;
        int col4 = (idx & 7) << 2;
        *(float4*)&WhS[row * SCH + col4] =
            *(const float4*)&Whb[(long)row * FF + c0 + col4];
    }
    __syncthreads();

    int warp = threadIdx.x >> 5;
    int lane = threadIdx.x & 31;
    for (int i = warp; i < NN; i += 8) {
        int n = nnz[i];
        const int* crow = cols + i * MAXN;
        const float* prow = Pc + ((long)b * NN + i) * MAXN;
        float a0 = 0.f, a1 = 0.f;
        int k = 0;
        for (; k + 2 <= n; k += 2) {
            int j0 = crow[k], j1 = crow[k + 1];
            float w0 = prow[k], w1 = prow[k + 1];
            a0 += w0 * WhS[j0 * SCH + lane];
            a1 += w1 * WhS[j1 * SCH + lane];
        }
        if (k < n) a0 += prow[k] * WhS[crow[k] * SCH + lane];
        float a = a0 + a1;
        if (epi >= 1) a = (a >= 0.f) ? a : expm1f(a);
        if (epi == 2) a = (a >= 0.f) ? a : expm1f(a);
        long o = cOff + (long)i * ldc + c0 + lane;
        __half h, l; split_h(a, h, l);
        Chi[o] = h; Clo[o] = l;
        if (writeF) Cf[o] = a;
    }
}

// ---------------- final pool ----------------
__global__ void pool_kernel(const float* __restrict__ x, const float* __restrict__ Wo,
                            const float* __restrict__ bo, float* __restrict__ out) {
    int t = blockIdx.x;
    int f = threadIdx.x;
    __shared__ float m[FF];
    const float* xt = x + (long)t * NN * FF;
    float s = 0.f;
    for (int n = 0; n < NN; n++) s += xt[n * FF + f];
    m[f] = s * (1.0f / NN);
    __syncthreads();
    float o = bo[f];
    for (int k = 0; k < FF; k++) o += m[k] * Wo[k * FF + f];
    out[t * FF + f] = o;
}

// ---------------- host orchestration ----------------
extern "C" void kernel_launch(void* const* d_in, const int* in_sizes, int n_in,
                              void* d_out, int out_size) {
    const float* pose    = (const float*)d_in[0];
    const int*   adj     = (const int*)  d_in[1];
    const float* Wp      = (const float*)d_in[2];
    const float* bp      = (const float*)d_in[3];
    const float* W_heads = (const float*)d_in[4];
    const float* a_heads = (const float*)d_in[5];
    const float* W_out   = (const float*)d_in[6];
    const float* a_out   = (const float*)d_in[7];
    const float* Wo      = (const float*)d_in[8];
    const float* bo      = (const float*)d_in[9];
    float* out = (float*)d_out;

    float *x, *Wh, *fb, *gb, *P;
    __half *xh, *xl, *xch, *xcl, *Wth, *Woth;
    int *nnz, *colsArr;
    cudaGetSymbolAddress((void**)&x,    g_x);
    cudaGetSymbolAddress((void**)&Wh,   g_Wh);
    cudaGetSymbolAddress((void**)&xh,   g_xh);
    cudaGetSymbolAddress((void**)&xl,   g_xl);
    cudaGetSymbolAddress((void**)&xch,  g_xch);
    cudaGetSymbolAddress((void**)&xcl,  g_xcl);
    cudaGetSymbolAddress((void**)&Wth,  g_Wth);
    cudaGetSymbolAddress((void**)&Woth, g_Woth);
    cudaGetSymbolAddress((void**)&fb,   g_f);
    cudaGetSymbolAddress((void**)&gb,   g_g);
    cudaGetSymbolAddress((void**)&P,    g_P);
    cudaGetSymbolAddress((void**)&nnz,  g_nnz);
    cudaGetSymbolAddress((void**)&colsArr, g_cols);

    static bool attrSet = false;
    if (!attrSet) {
        cudaFuncSetAttribute(spmm_kernel,
                             cudaFuncAttributeMaxDynamicSharedMemorySize, NN * SCH * 4);
        cudaFuncSetAttribute(gemm_tc,
                             cudaFuncAttributeMaxDynamicSharedMemorySize, GEMM_SMEM);
        attrSet = true;
    }

    adjlist_kernel<<<NN, 256>>>(adj, nnz, colsArr);

    {
        dim3 blk(32, 8);
        dim3 gh(FF / 32, FF / 32, LL * HH);
        wsplit_kernel<<<gh, blk>>>(W_heads, Wth, FF, FF);
        dim3 go(FF / 32, (HH * FF) / 32, LL);
        wsplit_kernel<<<go, blk>>>(W_out, Woth, HH * FF, FF);
    }

    {
        long total = (long)T_FR * NN * FF;
        input_proj_kernel<<<(unsigned)((total + 255) / 256), 256>>>(pose, Wp, bp, xh, xl);
    }

    for (int l = 0; l < LL; l++) {
        const __half* Wlh = Wth  + (long)l * HH * FF * FF;
        const __half* Woh = Woth + (long)l * FF * HH * FF;
        const float* al  = a_heads + (long)l * HH * 2 * FF;
        const float* aol = a_out   + (long)l * 2 * FF;

        // 2a. Wh = x @ W_heads  (fused f/g)
        zero_fg_kernel<<<(T_FR * HH * NN + 255) / 256, 256>>>(fb, gb, T_FR * HH * NN);
        {
            dim3 grid(FF / 128, NN / 128, T_FR * HH);
            gemm_tc<<<grid, 256, GEMM_SMEM>>>(xh, xl, Wlh, Wh,
                FF, FF, FF, FF,
                (long)NN * FF, HH,
                (long)FF * FF, HH,
                (long)NN * FF, 1, 0,
                0, fb, gb, al, HH, 1);
        }
        // 2c. sparse softmax -> compact P
        {
            int rows = T_FR * HH * NN;
            softmax_sparse_kernel<<<(rows * 32 + 255) / 256, 256>>>(fb, gb, nnz, colsArr, P, rows);
        }
        // 2d. xcat = elu(P @ Wh) -> fp16 hi/lo
        {
            dim3 grid(FF / SCH, T_FR * HH);
            spmm_kernel<<<grid, 256, NN * SCH * 4>>>(P, Wh, nnz, colsArr,
                xch, xcl, (float*)0, 0,
                (long)NN * FF,
                (long)NN * HH * FF, HH, FF, HH * FF, 1);
        }
        // 2e. Whout = xcat @ W_out  (K=2048, fused f/g)
        zero_fg_kernel<<<(T_FR * NN + 255) / 256, 256>>>(fb, gb, T_FR * NN);
        {
            dim3 grid(FF / 128, NN / 128, T_FR);
            gemm_tc<<<grid, 256, GEMM_SMEM>>>(xch, xcl, Woh, Wh,
                HH * FF, HH * FF, HH * FF, FF,
                (long)NN * HH * FF, 1,
                0, 1,
                (long)NN * FF, 1, 0,
                0, fb, gb, aol, 1, 1);
        }
        // 2g. sparse softmax -> compact P
        {
            int rows = T_FR * NN;
            softmax_sparse_kernel<<<(rows * 32 + 255) / 256, 256>>>(fb, gb, nnz, colsArr, P, rows);
        }
        // 2h. x = elu(elu(P @ Whout)) -> fp16 hi/lo (+ fp32 last layer)
        {
            dim3 grid(FF / SCH, T_FR);
            spmm_kernel<<<grid, 256, NN * SCH * 4>>>(P, Wh, nnz, colsArr,
                xh, xl, x, (l == LL - 1) ? 1 : 0,
                (long)NN * FF,
                (long)NN * FF, 1, 0, FF, 2);
        }
    }

    pool_kernel<<<T_FR, 256>>>(x, Wo, bo, out);
}

// round 13
// speedup vs baseline: 1.2003x; 1.1141x over previous
#include <cuda_runtime.h>
#include <cuda_fp16.h>
#include <math.h>
#include <stdint.h>

// Problem constants
#define T_FR 32
#define NN 512
#define FF 256
#define HH 8
#define LL 3
#define DIN 3
#define MAXN 128
#define SCH 32   // spmm column chunk

// ---------------- scratch (device globals; allocation-free rule) ----------------
__device__ float  g_x[T_FR * NN * FF];
__device__ float  g_Wh[T_FR * HH * NN * FF];
__device__ __half g_xh[T_FR * NN * FF];
__device__ __half g_xch[T_FR * NN * HH * FF];
__device__ __half g_Wth[LL * HH * FF * FF];     // W_heads^T [l][h][n][k] fp16
__device__ __half g_Woth[LL * FF * HH * FF];    // W_out^T   [l][n][k]    fp16
__device__ float  g_f[T_FR * HH * NN];
__device__ float  g_g[T_FR * HH * NN];
__device__ float  g_P[(long)T_FR * HH * NN * MAXN];
__device__ int    g_nnz[NN];
__device__ int    g_cols[NN * MAXN];

// ---------------- helpers ----------------
__device__ __forceinline__ uint32_t smem_u32(const void* p) {
    uint32_t a;
    asm("{ .reg .u64 t; cvta.to.shared.u64 t, %1; cvt.u32.u64 %0, t; }" : "=r"(a) : "l"(p));
    return a;
}
__device__ __forceinline__ void cp16(uint32_t dst, const void* src) {
    asm volatile("cp.async.cg.shared.global [%0], [%1], 16;" :: "r"(dst), "l"(src));
}
__device__ __forceinline__ void ldsm4(uint32_t* r, uint32_t addr) {
    asm volatile("ldmatrix.sync.aligned.m8n8.x4.shared.b16 {%0,%1,%2,%3}, [%4];"
        : "=r"(r[0]), "=r"(r[1]), "=r"(r[2]), "=r"(r[3]) : "r"(addr));
}
__device__ __forceinline__ void mma_fp16(float* c, const uint32_t* a, const uint32_t* b) {
    asm volatile("mma.sync.aligned.m16n8k16.row.col.f32.f16.f16.f32 "
        "{%0,%1,%2,%3}, {%4,%5,%6,%7}, {%8,%9}, {%0,%1,%2,%3};"
        : "+f"(c[0]), "+f"(c[1]), "+f"(c[2]), "+f"(c[3])
        : "r"(a[0]), "r"(a[1]), "r"(a[2]), "r"(a[3]), "r"(b[0]), "r"(b[1]));
}

// ---------------- input projection -> fp16 ----------------
__global__ void input_proj_kernel(const float* __restrict__ pose,
                                  const float* __restrict__ Wp,
                                  const float* __restrict__ bp,
                                  __half* __restrict__ xh) {
    long idx = (long)blockIdx.x * blockDim.x + threadIdx.x;
    if (idx >= (long)T_FR * NN * FF) return;
    int f = (int)(idx % FF);
    long tn = idx / FF;
    const float* p = pose + tn * DIN;
    float v = p[0] * Wp[f] + p[1] * Wp[FF + f] + p[2] * Wp[2 * FF + f] + bp[f];
    xh[idx] = __float2half_rn(v);
}

// ---------------- weight transpose: W [K][N] fp32 -> Wt [N][K] fp16 ----------------
__global__ void wsplit_kernel(const float* __restrict__ W,
                              __half* __restrict__ hi, int K, int N) {
    __shared__ float tile[32][33];
    int b = blockIdx.z;
    const float* Wb = W + (long)b * K * N;
    __half* hb = hi + (long)b * K * N;
    int kb = blockIdx.y * 32, nb = blockIdx.x * 32;
    for (int r = threadIdx.y; r < 32; r += 8)
        tile[r][threadIdx.x] = Wb[(long)(kb + r) * N + nb + threadIdx.x];
    __syncthreads();
    for (int r = threadIdx.y; r < 32; r += 8) {
        float v = tile[threadIdx.x][r];
        long o = (long)(nb + r) * K + kb + threadIdx.x;
        hb[o] = __float2half_rn(v);
    }
}

// ---------------- adjacency -> padded neighbor lists ----------------
__global__ void adjlist_kernel(const int* __restrict__ adj,
                               int* __restrict__ nnz, int* __restrict__ cols) {
    __shared__ int cnt;
    int i = blockIdx.x;
    if (threadIdx.x == 0) cnt = 0;
    __syncthreads();
    for (int j = threadIdx.x; j < NN; j += blockDim.x) {
        if (adj[(long)i * NN + j] > 0) {
            int p = atomicAdd(&cnt, 1);
            if (p < MAXN) cols[i * MAXN + p] = j;
        }
    }
    __syncthreads();
    if (threadIdx.x == 0) nnz[i] = (cnt < MAXN) ? cnt : MAXN;
}

// ---------------- zero f/g accumulators ----------------
__global__ void zero_fg_kernel(float* __restrict__ f, float* __restrict__ g, int n) {
    int i = blockIdx.x * blockDim.x + threadIdx.x;
    if (i < n) { f[i] = 0.f; g[i] = 0.f; }
}

// ============================================================================
// fp16 1-pass tensor-core GEMM: C = Ah @ Bh^T, fused f/g epilogue.
// CTA tile 128x128, warp tile 32x64, BK=32, 3-stage cp.async, 1 sync/iter.
// Stage (halfs): A 0..5119, B 5120..10239; STG 10240 -> 61.4 KB -> 3 CTAs/SM.
// ============================================================================
#define BOF 5120
#define STG 10240
#define GEMM_SMEM (3 * STG * 2)   // 61440 bytes

__global__ __launch_bounds__(256)
void gemm_tc(const __half* __restrict__ Ah, const __half* __restrict__ Bh,
             float* __restrict__ C,
             int K, int lda, int ldb, int ldc,
             long aStride, int aDiv, long bStride, int bMod,
             long cOuter, int cDiv, long cInner, int epi,
             float* __restrict__ fOut, float* __restrict__ gOut,
             const float* __restrict__ aVec, int aMod, int fgEnable) {
    extern __shared__ __align__(16) unsigned short smg[];
    uint32_t sb = smem_u32(smg);

    int tid = threadIdx.x;
    int lane = tid & 31;
    int warp = tid >> 5;
    int wm = warp >> 1;        // 0..3 -> rows wm*32
    int wn = warp & 1;         // 0..1 -> cols wn*64
    int g = lane >> 2;
    int q = lane & 3;

    int b = blockIdx.z;
    int col0 = blockIdx.x * 128;
    int row0 = blockIdx.y * 128;
    const __half* AhB = Ah + (long)(b / aDiv) * aStride;
    const __half* BhB = Bh + (long)(b % bMod) * bStride;
    float* Cb = C + (long)(b / cDiv) * cOuter + (long)(b % cDiv) * cInner;

    float acc[2][8][4];
    #pragma unroll
    for (int i = 0; i < 2; i++)
        #pragma unroll
        for (int j = 0; j < 8; j++)
            #pragma unroll
            for (int k = 0; k < 4; k++) acc[i][j][k] = 0.f;

    int arow0 = tid >> 2, aseg = tid & 3;
    int aRowA = (lane & 15);
    int kHalf = (lane >> 4) << 3;

    auto issue_stage = [&](int k0, int st) {
        uint32_t base = sb + (uint32_t)(st * STG * 2);
        #pragma unroll
        for (int h = 0; h < 2; h++) {
            int row = arow0 + h * 64;
            uint32_t d = base + (uint32_t)((row * 40 + aseg * 8) * 2);
            cp16(d, AhB + (long)(row0 + row) * lda + k0 + aseg * 8);
            cp16(d + BOF * 2, BhB + (long)(col0 + row) * ldb + k0 + aseg * 8);
        }
        asm volatile("cp.async.commit_group;");
    };

    int nIter = K >> 5;
    issue_stage(0, 0);
    issue_stage(32, 1);

    int slot = 0;
    for (int i = 0; i < nIter; i++) {
        if (i < nIter - 1) {
            asm volatile("cp.async.wait_group 1;");
        } else {
            asm volatile("cp.async.wait_group 0;");
        }
        __syncthreads();
        if (i + 2 < nIter) {
            int ws = slot + 2; if (ws >= 3) ws -= 3;
            issue_stage((i + 2) << 5, ws);
        }

        uint32_t stBase = sb + (uint32_t)(slot * STG * 2);
        #pragma unroll
        for (int kk = 0; kk < 32; kk += 16) {
            uint32_t ah[2][4], bf[8][2];
            #pragma unroll
            for (int mt = 0; mt < 2; mt++) {
                uint32_t addr = stBase + (uint32_t)(((wm * 32 + mt * 16 + aRowA) * 40 + kk + kHalf) * 2);
                ldsm4(ah[mt], addr);
            }
            #pragma unroll
            for (int ng = 0; ng < 4; ng++) {
                uint32_t r[4];
                uint32_t addr = stBase + (uint32_t)(((BOF) + (wn * 64 + ng * 16 + aRowA) * 40 + kk + kHalf) * 2);
                ldsm4(r, addr);
                bf[ng * 2 + 0][0] = r[0]; bf[ng * 2 + 0][1] = r[2];
                bf[ng * 2 + 1][0] = r[1]; bf[ng * 2 + 1][1] = r[3];
            }
            #pragma unroll
            for (int mt = 0; mt < 2; mt++)
                #pragma unroll
                for (int nt = 0; nt < 8; nt++) mma_fp16(acc[mt][nt], ah[mt], bf[nt]);
        }
        slot++; if (slot >= 3) slot = 0;
    }

    // ---- epilogue: store C (+epi), fused f/g partial dots ----
    float facc[4] = {0.f, 0.f, 0.f, 0.f};
    float gacc[4] = {0.f, 0.f, 0.f, 0.f};
    const float* av = fgEnable ? (aVec + (long)(b % aMod) * (2 * FF)) : (const float*)0;

    #pragma unroll
    for (int mt = 0; mt < 2; mt++) {
        #pragma unroll
        for (int nt = 0; nt < 8; nt++) {
            int r = row0 + wm * 32 + mt * 16 + g;
            int c = col0 + wn * 64 + nt * 8 + 2 * q;
            float v0 = acc[mt][nt][0], v1 = acc[mt][nt][1];
            float v2 = acc[mt][nt][2], v3 = acc[mt][nt][3];
            if (fgEnable) {
                float a10 = av[c], a11 = av[c + 1];
                float a20 = av[FF + c], a21 = av[FF + c + 1];
                facc[mt * 2 + 0] += v0 * a10 + v1 * a11;
                gacc[mt * 2 + 0] += v0 * a20 + v1 * a21;
                facc[mt * 2 + 1] += v2 * a10 + v3 * a11;
                gacc[mt * 2 + 1] += v2 * a20 + v3 * a21;
            }
            float vv[4] = {v0, v1, v2, v3};
            #pragma unroll
            for (int j = 0; j < 4; j++) {
                float u = vv[j];
                if (epi >= 1) u = (u >= 0.f) ? u : expm1f(u);
                if (epi == 2) u = (u >= 0.f) ? u : expm1f(u);
                vv[j] = u;
            }
            *(float2*)&Cb[(long)r * ldc + c] = make_float2(vv[0], vv[1]);
            *(float2*)&Cb[(long)(r + 8) * ldc + c] = make_float2(vv[2], vv[3]);
        }
    }
    if (fgEnable) {
        #pragma unroll
        for (int idx = 0; idx < 4; idx++) {
            facc[idx] += __shfl_xor_sync(0xffffffffu, facc[idx], 1);
            facc[idx] += __shfl_xor_sync(0xffffffffu, facc[idx], 2);
            gacc[idx] += __shfl_xor_sync(0xffffffffu, gacc[idx], 1);
            gacc[idx] += __shfl_xor_sync(0xffffffffu, gacc[idx], 2);
        }
        if (q == 0) {
            #pragma unroll
            for (int mt = 0; mt < 2; mt++) {
                #pragma unroll
                for (int s = 0; s < 2; s++) {
                    int row = row0 + wm * 32 + mt * 16 + g + s * 8;
                    long w = (long)b * NN + row;
                    atomicAdd(&fOut[w], facc[mt * 2 + s]);
                    atomicAdd(&gOut[w], gacc[mt * 2 + s]);
                }
            }
        }
    }
}

// ---------------- sparse softmax over neighbor lists ----------------
__global__ void softmax_sparse_kernel(const float* __restrict__ f, const float* __restrict__ g,
                                      const int* __restrict__ nnz, const int* __restrict__ cols,
                                      float* __restrict__ Pc, int totalRows) {
    int w = (int)(((long)blockIdx.x * blockDim.x + threadIdx.x) >> 5);
    int lane = threadIdx.x & 31;
    if (w >= totalRows) return;
    int b = w >> 9;
    int i = w & 511;
    float fi = f[w];
    const float* gb = g + (long)b * NN;
    int n = nnz[i];
    const int* crow = cols + i * MAXN;
    int nc = (n + 31) >> 5;

    float e[4];
    float mx = -INFINITY;
    for (int c = 0; c < nc; c++) {
        int k = c * 32 + lane;
        float v = -INFINITY;
        if (k < n) {
            float xv = fi + gb[crow[k]];
            v = (xv >= 0.f) ? xv : 0.2f * xv;
        }
        e[c] = v;
        mx = fmaxf(mx, v);
    }
    #pragma unroll
    for (int o = 16; o > 0; o >>= 1) mx = fmaxf(mx, __shfl_xor_sync(0xffffffffu, mx, o));

    float s = 0.f;
    for (int c = 0; c < nc; c++) {
        float ev = (e[c] > -1e30f) ? __expf(e[c] - mx) : 0.f;
        e[c] = ev; s += ev;
    }
    #pragma unroll
    for (int o = 16; o > 0; o >>= 1) s += __shfl_xor_sync(0xffffffffu, s, o);
    float inv = 1.0f / s;

    float* prow = Pc + (long)w * MAXN;
    for (int c = 0; c < nc; c++) {
        int k = c * 32 + lane;
        if (k < n) prow[k] = e[c] * inv;
    }
}

// ---------------- sparse attention apply; 32-col chunks, dual accumulators ----------------
__global__ __launch_bounds__(256)
void spmm_kernel(const float* __restrict__ Pc, const float* __restrict__ Wh,
                 const int* __restrict__ nnz, const int* __restrict__ cols,
                 __half* __restrict__ Chi,
                 float* __restrict__ Cf, int writeF,
                 long whStride, long cOuter, int cDiv, long cInner, int ldc, int epi) {
    extern __shared__ float WhS[];     // [NN][SCH]
    int b = blockIdx.y;
    int c0 = blockIdx.x * SCH;
    const float* Whb = Wh + (long)b * whStride;
    long cOff = (long)(b / cDiv) * cOuter + (long)(b % cDiv) * cInner;

    for (int idx = threadIdx.x; idx < NN * (SCH / 4); idx += 256) {
        int row = idx >> 3;
        int col4 = (idx & 7) << 2;
        *(float4*)&WhS[row * SCH + col4] =
            *(const float4*)&Whb[(long)row * FF + c0 + col4];
    }
    __syncthreads();

    int warp = threadIdx.x >> 5;
    int lane = threadIdx.x & 31;
    for (int i = warp; i < NN; i += 8) {
        int n = nnz[i];
        const int* crow = cols + i * MAXN;
        const float* prow = Pc + ((long)b * NN + i) * MAXN;
        float a0 = 0.f, a1 = 0.f;
        int k = 0;
        for (; k + 2 <= n; k += 2) {
            int j0 = crow[k], j1 = crow[k + 1];
            float w0 = prow[k], w1 = prow[k + 1];
            a0 += w0 * WhS[j0 * SCH + lane];
            a1 += w1 * WhS[j1 * SCH + lane];
        }
        if (k < n) a0 += prow[k] * WhS[crow[k] * SCH + lane];
        float a = a0 + a1;
        if (epi >= 1) a = (a >= 0.f) ? a : expm1f(a);
        if (epi == 2) a = (a >= 0.f) ? a : expm1f(a);
        long o = cOff + (long)i * ldc + c0 + lane;
        Chi[o] = __float2half_rn(a);
        if (writeF) Cf[o] = a;
    }
}

// ---------------- final pool ----------------
__global__ void pool_kernel(const float* __restrict__ x, const float* __restrict__ Wo,
                            const float* __restrict__ bo, float* __restrict__ out) {
    int t = blockIdx.x;
    int f = threadIdx.x;
    __shared__ float m[FF];
    const float* xt = x + (long)t * NN * FF;
    float s = 0.f;
    for (int n = 0; n < NN; n++) s += xt[n * FF + f];
    m[f] = s * (1.0f / NN);
    __syncthreads();
    float o = bo[f];
    for (int k = 0; k < FF; k++) o += m[k] * Wo[k * FF + f];
    out[t * FF + f] = o;
}

// ---------------- host orchestration ----------------
extern "C" void kernel_launch(void* const* d_in, const int* in_sizes, int n_in,
                              void* d_out, int out_size) {
    const float* pose    = (const float*)d_in[0];
    const int*   adj     = (const int*)  d_in[1];
    const float* Wp      = (const float*)d_in[2];
    const float* bp      = (const float*)d_in[3];
    const float* W_heads = (const float*)d_in[4];
    const float* a_heads = (const float*)d_in[5];
    const float* W_out   = (const float*)d_in[6];
    const float* a_out   = (const float*)d_in[7];
    const float* Wo      = (const float*)d_in[8];
    const float* bo      = (const float*)d_in[9];
    float* out = (float*)d_out;

    float *x, *Wh, *fb, *gb, *P;
    __half *xh, *xch, *Wth, *Woth;
    int *nnz, *colsArr;
    cudaGetSymbolAddress((void**)&x,    g_x);
    cudaGetSymbolAddress((void**)&Wh,   g_Wh);
    cudaGetSymbolAddress((void**)&xh,   g_xh);
    cudaGetSymbolAddress((void**)&xch,  g_xch);
    cudaGetSymbolAddress((void**)&Wth,  g_Wth);
    cudaGetSymbolAddress((void**)&Woth, g_Woth);
    cudaGetSymbolAddress((void**)&fb,   g_f);
    cudaGetSymbolAddress((void**)&gb,   g_g);
    cudaGetSymbolAddress((void**)&P,    g_P);
    cudaGetSymbolAddress((void**)&nnz,  g_nnz);
    cudaGetSymbolAddress((void**)&colsArr, g_cols);

    static bool attrSet = false;
    if (!attrSet) {
        cudaFuncSetAttribute(spmm_kernel,
                             cudaFuncAttributeMaxDynamicSharedMemorySize, NN * SCH * 4);
        cudaFuncSetAttribute(gemm_tc,
                             cudaFuncAttributeMaxDynamicSharedMemorySize, GEMM_SMEM);
        attrSet = true;
    }

    adjlist_kernel<<<NN, 256>>>(adj, nnz, colsArr);

    {
        dim3 blk(32, 8);
        dim3 gh(FF / 32, FF / 32, LL * HH);
        wsplit_kernel<<<gh, blk>>>(W_heads, Wth, FF, FF);
        dim3 go(FF / 32, (HH * FF) / 32, LL);
        wsplit_kernel<<<go, blk>>>(W_out, Woth, HH * FF, FF);
    }

    {
        long total = (long)T_FR * NN * FF;
        input_proj_kernel<<<(unsigned)((total + 255) / 256), 256>>>(pose, Wp, bp, xh);
    }

    for (int l = 0; l < LL; l++) {
        const __half* Wlh = Wth  + (long)l * HH * FF * FF;
        const __half* Woh = Woth + (long)l * FF * HH * FF;
        const float* al  = a_heads + (long)l * HH * 2 * FF;
        const float* aol = a_out   + (long)l * 2 * FF;

        // 2a. Wh = x @ W_heads  (1-pass fp16, fused f/g)
        zero_fg_kernel<<<(T_FR * HH * NN + 255) / 256, 256>>>(fb, gb, T_FR * HH * NN);
        {
            dim3 grid(FF / 128, NN / 128, T_FR * HH);
            gemm_tc<<<grid, 256, GEMM_SMEM>>>(xh, Wlh, Wh,
                FF, FF, FF, FF,
                (long)NN * FF, HH,
                (long)FF * FF, HH,
                (long)NN * FF, 1, 0,
                0, fb, gb, al, HH, 1);
        }
        // 2c. sparse softmax -> compact P
        {
            int rows = T_FR * HH * NN;
            softmax_sparse_kernel<<<(rows * 32 + 255) / 256, 256>>>(fb, gb, nnz, colsArr, P, rows);
        }
        // 2d. xcat = elu(P @ Wh) -> fp16
        {
            dim3 grid(FF / SCH, T_FR * HH);
            spmm_kernel<<<grid, 256, NN * SCH * 4>>>(P, Wh, nnz, colsArr,
                xch, (float*)0, 0,
                (long)NN * FF,
                (long)NN * HH * FF, HH, FF, HH * FF, 1);
        }
        // 2e. Whout = xcat @ W_out  (1-pass fp16, K=2048, fused f/g)
        zero_fg_kernel<<<(T_FR * NN + 255) / 256, 256>>>(fb, gb, T_FR * NN);
        {
            dim3 grid(FF / 128, NN / 128, T_FR);
            gemm_tc<<<grid, 256, GEMM_SMEM>>>(xch, Woh, Wh,
                HH * FF, HH * FF, HH * FF, FF,
                (long)NN * HH * FF, 1,
                0, 1,
                (long)NN * FF, 1, 0,
                0, fb, gb, aol, 1, 1);
        }
        // 2g. sparse softmax -> compact P
        {
            int rows = T_FR * NN;
            softmax_sparse_kernel<<<(rows * 32 + 255) / 256, 256>>>(fb, gb, nnz, colsArr, P, rows);
        }
        // 2h. x = elu(elu(P @ Whout)) -> fp16 (+ fp32 last layer)
        {
            dim3 grid(FF / SCH, T_FR);
            spmm_kernel<<<grid, 256, NN * SCH * 4>>>(P, Wh, nnz, colsArr,
                xh, x, (l == LL - 1) ? 1 : 0,
                (long)NN * FF,
                (long)NN * FF, 1, 0, FF, 2);
        }
    }

    pool_kernel<<<T_FR, 256>>>(x, Wo, bo, out);
}

// round 14
// speedup vs baseline: 1.2185x; 1.0152x over previous
#include <cuda_runtime.h>
#include <cuda_fp16.h>
#include <math.h>
#include <stdint.h>

// Problem constants
#define T_FR 32
#define NN 512
#define FF 256
#define HH 8
#define LL 3
#define DIN 3
#define MAXN 128
#define SCH 32   // spmm column chunk

// ---------------- scratch (device globals; allocation-free rule) ----------------
__device__ float  g_x[T_FR * NN * FF];
__device__ float  g_Wh[T_FR * HH * NN * FF];
__device__ __half g_xh[T_FR * NN * FF];
__device__ __half g_xch[T_FR * NN * HH * FF];
__device__ __half g_Wth[LL * HH * FF * FF];     // W_heads^T [l][h][n][k] fp16
__device__ __half g_Woth[LL * FF * HH * FF];    // W_out^T   [l][n][k]    fp16
__device__ float  g_f[T_FR * HH * NN];
__device__ float  g_g[T_FR * HH * NN];
__device__ float  g_P[(long)T_FR * HH * NN * MAXN];
__device__ int    g_nnz[NN];
__device__ int    g_cols[NN * MAXN];

// ---------------- helpers ----------------
__device__ __forceinline__ uint32_t smem_u32(const void* p) {
    uint32_t a;
    asm("{ .reg .u64 t; cvta.to.shared.u64 t, %1; cvt.u32.u64 %0, t; }" : "=r"(a) : "l"(p));
    return a;
}
__device__ __forceinline__ void cp16(uint32_t dst, const void* src) {
    asm volatile("cp.async.cg.shared.global [%0], [%1], 16;" :: "r"(dst), "l"(src));
}
__device__ __forceinline__ void ldsm4(uint32_t* r, uint32_t addr) {
    asm volatile("ldmatrix.sync.aligned.m8n8.x4.shared.b16 {%0,%1,%2,%3}, [%4];"
        : "=r"(r[0]), "=r"(r[1]), "=r"(r[2]), "=r"(r[3]) : "r"(addr));
}
__device__ __forceinline__ void mma_fp16(float* c, const uint32_t* a, const uint32_t* b) {
    asm volatile("mma.sync.aligned.m16n8k16.row.col.f32.f16.f16.f32 "
        "{%0,%1,%2,%3}, {%4,%5,%6,%7}, {%8,%9}, {%0,%1,%2,%3};"
        : "+f"(c[0]), "+f"(c[1]), "+f"(c[2]), "+f"(c[3])
        : "r"(a[0]), "r"(a[1]), "r"(a[2]), "r"(a[3]), "r"(b[0]), "r"(b[1]));
}

// ---------------- input projection -> fp16 ----------------
__global__ void input_proj_kernel(const float* __restrict__ pose,
                                  const float* __restrict__ Wp,
                                  const float* __restrict__ bp,
                                  __half* __restrict__ xh) {
    long idx = (long)blockIdx.x * blockDim.x + threadIdx.x;
    if (idx >= (long)T_FR * NN * FF) return;
    int f = (int)(idx % FF);
    long tn = idx / FF;
    const float* p = pose + tn * DIN;
    float v = p[0] * Wp[f] + p[1] * Wp[FF + f] + p[2] * Wp[2 * FF + f] + bp[f];
    xh[idx] = __float2half_rn(v);
}

// ---------------- weight transpose: W [K][N] fp32 -> Wt [N][K] fp16 ----------------
__global__ void wsplit_kernel(const float* __restrict__ W,
                              __half* __restrict__ hi, int K, int N) {
    __shared__ float tile[32][33];
    int b = blockIdx.z;
    const float* Wb = W + (long)b * K * N;
    __half* hb = hi + (long)b * K * N;
    int kb = blockIdx.y * 32, nb = blockIdx.x * 32;
    for (int r = threadIdx.y; r < 32; r += 8)
        tile[r][threadIdx.x] = Wb[(long)(kb + r) * N + nb + threadIdx.x];
    __syncthreads();
    for (int r = threadIdx.y; r < 32; r += 8) {
        float v = tile[threadIdx.x][r];
        long o = (long)(nb + r) * K + kb + threadIdx.x;
        hb[o] = __float2half_rn(v);
    }
}

// ---------------- adjacency -> padded neighbor lists ----------------
__global__ void adjlist_kernel(const int* __restrict__ adj,
                               int* __restrict__ nnz, int* __restrict__ cols) {
    __shared__ int cnt;
    int i = blockIdx.x;
    if (threadIdx.x == 0) cnt = 0;
    __syncthreads();
    for (int j = threadIdx.x; j < NN; j += blockDim.x) {
        if (adj[(long)i * NN + j] > 0) {
            int p = atomicAdd(&cnt, 1);
            if (p < MAXN) cols[i * MAXN + p] = j;
        }
    }
    __syncthreads();
    if (threadIdx.x == 0) nnz[i] = (cnt < MAXN) ? cnt : MAXN;
}

// ---------------- zero f/g accumulators ----------------
__global__ void zero_fg_kernel(float* __restrict__ f, float* __restrict__ g, int n) {
    int i = blockIdx.x * blockDim.x + threadIdx.x;
    if (i < n) { f[i] = 0.f; g[i] = 0.f; }
}

// ============================================================================
// fp16 1-pass tensor-core GEMM: C = Ah @ Bh^T, fused f/g epilogue.
// CTA tile 128x64, warp tile 32x32 (8 warps = 4M x 2N), BK=32,
// 3-stage cp.async, 1 sync/iter. Stage = (128+64) rows * 40 halfs = 15.4 KB.
// Low register footprint (acc=16) -> >=3 CTAs/SM.
// ============================================================================
#define BOF 5120                 // B rows start at 128*40 halfs
#define STG 7680                 // 192 * 40 halfs
#define GEMM_SMEM (3 * STG * 2)  // 46080 bytes

__global__ __launch_bounds__(256, 3)
void gemm_tc(const __half* __restrict__ Ah, const __half* __restrict__ Bh,
             float* __restrict__ C,
             int K, int lda, int ldb, int ldc,
             long aStride, int aDiv, long bStride, int bMod,
             long cOuter, int cDiv, long cInner, int epi,
             float* __restrict__ fOut, float* __restrict__ gOut,
             const float* __restrict__ aVec, int aMod, int fgEnable) {
    extern __shared__ __align__(16) unsigned short smg[];
    uint32_t sb = smem_u32(smg);

    int tid = threadIdx.x;
    int lane = tid & 31;
    int warp = tid >> 5;
    int wm = warp >> 1;        // 0..3 -> rows wm*32
    int wn = warp & 1;         // 0..1 -> cols wn*32
    int g = lane >> 2;
    int q = lane & 3;

    int b = blockIdx.z;
    int col0 = blockIdx.x * 64;
    int row0 = blockIdx.y * 128;
    const __half* AhB = Ah + (long)(b / aDiv) * aStride;
    const __half* BhB = Bh + (long)(b % bMod) * bStride;
    float* Cb = C + (long)(b / cDiv) * cOuter + (long)(b % cDiv) * cInner;

    float acc[2][4][4];
    #pragma unroll
    for (int i = 0; i < 2; i++)
        #pragma unroll
        for (int j = 0; j < 4; j++)
            #pragma unroll
            for (int k = 0; k < 4; k++) acc[i][j][k] = 0.f;

    int aRowA = (lane & 15);
    int kHalf = (lane >> 4) << 3;

    // 192 rows * 4 segs = 768 cp16-pairs per stage; 3 per thread
    auto issue_stage = [&](int k0, int st) {
        uint32_t base = sb + (uint32_t)(st * STG * 2);
        #pragma unroll
        for (int it = 0; it < 3; it++) {
            int idx = tid + it * 256;       // 0..767
            int r = idx >> 2;               // 0..191
            int seg = idx & 3;
            uint32_t d = base + (uint32_t)((r * 40 + seg * 8) * 2);
            if (r < 128) {
                cp16(d, AhB + (long)(row0 + r) * lda + k0 + seg * 8);
            } else {
                cp16(d, BhB + (long)(col0 + r - 128) * ldb + k0 + seg * 8);
            }
        }
        asm volatile("cp.async.commit_group;");
    };

    int nIter = K >> 5;
    issue_stage(0, 0);
    issue_stage(32, 1);

    int slot = 0;
    for (int i = 0; i < nIter; i++) {
        if (i < nIter - 1) {
            asm volatile("cp.async.wait_group 1;");
        } else {
            asm volatile("cp.async.wait_group 0;");
        }
        __syncthreads();
        if (i + 2 < nIter) {
            int ws = slot + 2; if (ws >= 3) ws -= 3;
            issue_stage((i + 2) << 5, ws);
        }

        uint32_t stBase = sb + (uint32_t)(slot * STG * 2);
        #pragma unroll
        for (int kk = 0; kk < 32; kk += 16) {
            uint32_t ah[2][4], bf[4][2];
            #pragma unroll
            for (int mt = 0; mt < 2; mt++) {
                uint32_t addr = stBase + (uint32_t)(((wm * 32 + mt * 16 + aRowA) * 40 + kk + kHalf) * 2);
                ldsm4(ah[mt], addr);
            }
            #pragma unroll
            for (int ng = 0; ng < 2; ng++) {
                uint32_t r[4];
                uint32_t addr = stBase + (uint32_t)(((BOF) + (wn * 32 + ng * 16 + aRowA) * 40 + kk + kHalf) * 2);
                ldsm4(r, addr);
                bf[ng * 2 + 0][0] = r[0]; bf[ng * 2 + 0][1] = r[2];
                bf[ng * 2 + 1][0] = r[1]; bf[ng * 2 + 1][1] = r[3];
            }
            #pragma unroll
            for (int mt = 0; mt < 2; mt++)
                #pragma unroll
                for (int nt = 0; nt < 4; nt++) mma_fp16(acc[mt][nt], ah[mt], bf[nt]);
        }
        slot++; if (slot >= 3) slot = 0;
    }

    // ---- epilogue: store C (+epi), fused f/g partial dots ----
    float facc[4] = {0.f, 0.f, 0.f, 0.f};
    float gacc[4] = {0.f, 0.f, 0.f, 0.f};
    const float* av = fgEnable ? (aVec + (long)(b % aMod) * (2 * FF)) : (const float*)0;

    #pragma unroll
    for (int mt = 0; mt < 2; mt++) {
        #pragma unroll
        for (int nt = 0; nt < 4; nt++) {
            int r = row0 + wm * 32 + mt * 16 + g;
            int c = col0 + wn * 32 + nt * 8 + 2 * q;
            float v0 = acc[mt][nt][0], v1 = acc[mt][nt][1];
            float v2 = acc[mt][nt][2], v3 = acc[mt][nt][3];
            if (fgEnable) {
                float a10 = av[c], a11 = av[c + 1];
                float a20 = av[FF + c], a21 = av[FF + c + 1];
                facc[mt * 2 + 0] += v0 * a10 + v1 * a11;
                gacc[mt * 2 + 0] += v0 * a20 + v1 * a21;
                facc[mt * 2 + 1] += v2 * a10 + v3 * a11;
                gacc[mt * 2 + 1] += v2 * a20 + v3 * a21;
            }
            float vv[4] = {v0, v1, v2, v3};
            #pragma unroll
            for (int j = 0; j < 4; j++) {
                float u = vv[j];
                if (epi >= 1) u = (u >= 0.f) ? u : expm1f(u);
                if (epi == 2) u = (u >= 0.f) ? u : expm1f(u);
                vv[j] = u;
            }
            *(float2*)&Cb[(long)r * ldc + c] = make_float2(vv[0], vv[1]);
            *(float2*)&Cb[(long)(r + 8) * ldc + c] = make_float2(vv[2], vv[3]);
        }
    }
    if (fgEnable) {
        #pragma unroll
        for (int idx = 0; idx < 4; idx++) {
            facc[idx] += __shfl_xor_sync(0xffffffffu, facc[idx], 1);
            facc[idx] += __shfl_xor_sync(0xffffffffu, facc[idx], 2);
            gacc[idx] += __shfl_xor_sync(0xffffffffu, gacc[idx], 1);
            gacc[idx] += __shfl_xor_sync(0xffffffffu, gacc[idx], 2);
        }
        if (q == 0) {
            #pragma unroll
            for (int mt = 0; mt < 2; mt++) {
                #pragma unroll
                for (int s = 0; s < 2; s++) {
                    int row = row0 + wm * 32 + mt * 16 + g + s * 8;
                    long w = (long)b * NN + row;
                    atomicAdd(&fOut[w], facc[mt * 2 + s]);
                    atomicAdd(&gOut[w], gacc[mt * 2 + s]);
                }
            }
        }
    }
}

// ---------------- sparse softmax over neighbor lists ----------------
__global__ void softmax_sparse_kernel(const float* __restrict__ f, const float* __restrict__ g,
                                      const int* __restrict__ nnz, const int* __restrict__ cols,
                                      float* __restrict__ Pc, int totalRows) {
    int w = (int)(((long)blockIdx.x * blockDim.x + threadIdx.x) >> 5);
    int lane = threadIdx.x & 31;
    if (w >= totalRows) return;
    int b = w >> 9;
    int i = w & 511;
    float fi = f[w];
    const float* gb = g + (long)b * NN;
    int n = nnz[i];
    const int* crow = cols + i * MAXN;
    int nc = (n + 31) >> 5;

    float e[4];
    float mx = -INFINITY;
    for (int c = 0; c < nc; c++) {
        int k = c * 32 + lane;
        float v = -INFINITY;
        if (k < n) {
            float xv = fi + gb[crow[k]];
            v = (xv >= 0.f) ? xv : 0.2f * xv;
        }
        e[c] = v;
        mx = fmaxf(mx, v);
    }
    #pragma unroll
    for (int o = 16; o > 0; o >>= 1) mx = fmaxf(mx, __shfl_xor_sync(0xffffffffu, mx, o));

    float s = 0.f;
    for (int c = 0; c < nc; c++) {
        float ev = (e[c] > -1e30f) ? __expf(e[c] - mx) : 0.f;
        e[c] = ev; s += ev;
    }
    #pragma unroll
    for (int o = 16; o > 0; o >>= 1) s += __shfl_xor_sync(0xffffffffu, s, o);
    float inv = 1.0f / s;

    float* prow = Pc + (long)w * MAXN;
    for (int c = 0; c < nc; c++) {
        int k = c * 32 + lane;
        if (k < n) prow[k] = e[c] * inv;
    }
}

// ---------------- sparse attention apply; 32-col chunks, dual accumulators ----------------
__global__ __launch_bounds__(256)
void spmm_kernel(const float* __restrict__ Pc, const float* __restrict__ Wh,
                 const int* __restrict__ nnz, const int* __restrict__ cols,
                 __half* __restrict__ Chi,
                 float* __restrict__ Cf, int writeF,
                 long whStride, long cOuter, int cDiv, long cInner, int ldc, int epi) {
    extern __shared__ float WhS[];     // [NN][SCH]
    int b = blockIdx.y;
    int c0 = blockIdx.x * SCH;
    const float* Whb = Wh + (long)b * whStride;
    long cOff = (long)(b / cDiv) * cOuter + (long)(b % cDiv) * cInner;

    for (int idx = threadIdx.x; idx < NN * (SCH / 4); idx += 256) {
        int row = idx >> 3;
        int col4 = (idx & 7) << 2;
        *(float4*)&WhS[row * SCH + col4] =
            *(const float4*)&Whb[(long)row * FF + c0 + col4];
    }
    __syncthreads();

    int warp = threadIdx.x >> 5;
    int lane = threadIdx.x & 31;
    for (int i = warp; i < NN; i += 8) {
        int n = nnz[i];
        const int* crow = cols + i * MAXN;
        const float* prow = Pc + ((long)b * NN + i) * MAXN;
        float a0 = 0.f, a1 = 0.f;
        int k = 0;
        for (; k + 2 <= n; k += 2) {
            int j0 = crow[k], j1 = crow[k + 1];
            float w0 = prow[k], w1 = prow[k + 1];
            a0 += w0 * WhS[j0 * SCH + lane];
            a1 += w1 * WhS[j1 * SCH + lane];
        }
        if (k < n) a0 += prow[k] * WhS[crow[k] * SCH + lane];
        float a = a0 + a1;
        if (epi >= 1) a = (a >= 0.f) ? a : expm1f(a);
        if (epi == 2) a = (a >= 0.f) ? a : expm1f(a);
        long o = cOff + (long)i * ldc + c0 + lane;
        Chi[o] = __float2half_rn(a);
        if (writeF) Cf[o] = a;
    }
}

// ---------------- final pool ----------------
__global__ void pool_kernel(const float* __restrict__ x, const float* __restrict__ Wo,
                            const float* __restrict__ bo, float* __restrict__ out) {
    int t = blockIdx.x;
    int f = threadIdx.x;
    __shared__ float m[FF];
    const float* xt = x + (long)t * NN * FF;
    float s = 0.f;
    for (int n = 0; n < NN; n++) s += xt[n * FF + f];
    m[f] = s * (1.0f / NN);
    __syncthreads();
    float o = bo[f];
    for (int k = 0; k < FF; k++) o += m[k] * Wo[k * FF + f];
    out[t * FF + f] = o;
}

// ---------------- host orchestration ----------------
extern "C" void kernel_launch(void* const* d_in, const int* in_sizes, int n_in,
                              void* d_out, int out_size) {
    const float* pose    = (const float*)d_in[0];
    const int*   adj     = (const int*)  d_in[1];
    const float* Wp      = (const float*)d_in[2];
    const float* bp      = (const float*)d_in[3];
    const float* W_heads = (const float*)d_in[4];
    const float* a_heads = (const float*)d_in[5];
    const float* W_out   = (const float*)d_in[6];
    const float* a_out   = (const float*)d_in[7];
    const float* Wo      = (const float*)d_in[8];
    const float* bo      = (const float*)d_in[9];
    float* out = (float*)d_out;

    float *x, *Wh, *fb, *gb, *P;
    __half *xh, *xch, *Wth, *Woth;
    int *nnz, *colsArr;
    cudaGetSymbolAddress((void**)&x,    g_x);
    cudaGetSymbolAddress((void**)&Wh,   g_Wh);
    cudaGetSymbolAddress((void**)&xh,   g_xh);
    cudaGetSymbolAddress((void**)&xch,  g_xch);
    cudaGetSymbolAddress((void**)&Wth,  g_Wth);
    cudaGetSymbolAddress((void**)&Woth, g_Woth);
    cudaGetSymbolAddress((void**)&fb,   g_f);
    cudaGetSymbolAddress((void**)&gb,   g_g);
    cudaGetSymbolAddress((void**)&P,    g_P);
    cudaGetSymbolAddress((void**)&nnz,  g_nnz);
    cudaGetSymbolAddress((void**)&colsArr, g_cols);

    static bool attrSet = false;
    if (!attrSet) {
        cudaFuncSetAttribute(spmm_kernel,
                             cudaFuncAttributeMaxDynamicSharedMemorySize, NN * SCH * 4);
        cudaFuncSetAttribute(gemm_tc,
                             cudaFuncAttributeMaxDynamicSharedMemorySize, GEMM_SMEM);
        attrSet = true;
    }

    adjlist_kernel<<<NN, 256>>>(adj, nnz, colsArr);

    {
        dim3 blk(32, 8);
        dim3 gh(FF / 32, FF / 32, LL * HH);
        wsplit_kernel<<<gh, blk>>>(W_heads, Wth, FF, FF);
        dim3 go(FF / 32, (HH * FF) / 32, LL);
        wsplit_kernel<<<go, blk>>>(W_out, Woth, HH * FF, FF);
    }

    {
        long total = (long)T_FR * NN * FF;
        input_proj_kernel<<<(unsigned)((total + 255) / 256), 256>>>(pose, Wp, bp, xh);
    }

    for (int l = 0; l < LL; l++) {
        const __half* Wlh = Wth  + (long)l * HH * FF * FF;
        const __half* Woh = Woth + (long)l * FF * HH * FF;
        const float* al  = a_heads + (long)l * HH * 2 * FF;
        const float* aol = a_out   + (long)l * 2 * FF;

        // 2a. Wh = x @ W_heads  (1-pass fp16, fused f/g)
        zero_fg_kernel<<<(T_FR * HH * NN + 255) / 256, 256>>>(fb, gb, T_FR * HH * NN);
        {
            dim3 grid(FF / 64, NN / 128, T_FR * HH);
            gemm_tc<<<grid, 256, GEMM_SMEM>>>(xh, Wlh, Wh,
                FF, FF, FF, FF,
                (long)NN * FF, HH,
                (long)FF * FF, HH,
                (long)NN * FF, 1, 0,
                0, fb, gb, al, HH, 1);
        }
        // 2c. sparse softmax -> compact P
        {
            int rows = T_FR * HH * NN;
            softmax_sparse_kernel<<<(rows * 32 + 255) / 256, 256>>>(fb, gb, nnz, colsArr, P, rows);
        }
        // 2d. xcat = elu(P @ Wh) -> fp16
        {
            dim3 grid(FF / SCH, T_FR * HH);
            spmm_kernel<<<grid, 256, NN * SCH * 4>>>(P, Wh, nnz, colsArr,
                xch, (float*)0, 0,
                (long)NN * FF,
                (long)NN * HH * FF, HH, FF, HH * FF, 1);
        }
        // 2e. Whout = xcat @ W_out  (1-pass fp16, K=2048, fused f/g)
        zero_fg_kernel<<<(T_FR * NN + 255) / 256, 256>>>(fb, gb, T_FR * NN);
        {
            dim3 grid(FF / 64, NN / 128, T_FR);
            gemm_tc<<<grid, 256, GEMM_SMEM>>>(xch, Woh, Wh,
                HH * FF, HH * FF, HH * FF, FF,
                (long)NN * HH * FF, 1,
                0, 1,
                (long)NN * FF, 1, 0,
                0, fb, gb, aol, 1, 1);
        }
        // 2g. sparse softmax -> compact P
        {
            int rows = T_FR * NN;
            softmax_sparse_kernel<<<(rows * 32 + 255) / 256, 256>>>(fb, gb, nnz, colsArr, P, rows);
        }
        // 2h. x = elu(elu(P @ Whout)) -> fp16 (+ fp32 last layer)
        {
            dim3 grid(FF / SCH, T_FR);
            spmm_kernel<<<grid, 256, NN * SCH * 4>>>(P, Wh, nnz, colsArr,
                xh, x, (l == LL - 1) ? 1 : 0,
                (long)NN * FF,
                (long)NN * FF, 1, 0, FF, 2);
        }
    }

    pool_kernel<<<T_FR, 256>>>(x, Wo, bo, out);
}

// round 15
// speedup vs baseline: 1.2716x; 1.0436x over previous
#include <cuda_runtime.h>
#include <cuda_fp16.h>
#include <math.h>
#include <stdint.h>

// Problem constants
#define T_FR 32
#define NN 512
#define FF 256
#define HH 8
#define LL 3
#define DIN 3
#define MAXN 128
#define SCH 32   // spmm column chunk

// ---------------- scratch (device globals; allocation-free rule) ----------------
__device__ float  g_x[T_FR * NN * FF];
__device__ __half g_Whh[T_FR * HH * NN * FF];   // fp16 Wh intermediate
__device__ __half g_xh[T_FR * NN * FF];
__device__ __half g_xch[T_FR * NN * HH * FF];
__device__ __half g_Wth[LL * HH * FF * FF];     // W_heads^T [l][h][n][k] fp16
__device__ __half g_Woth[LL * FF * HH * FF];    // W_out^T   [l][n][k]    fp16
__device__ float  g_f[T_FR * HH * NN];
__device__ float  g_g[T_FR * HH * NN];
__device__ float  g_P[(long)T_FR * HH * NN * MAXN];
__device__ int    g_nnz[NN];
__device__ int    g_cols[NN * MAXN];

// ---------------- helpers ----------------
__device__ __forceinline__ uint32_t smem_u32(const void* p) {
    uint32_t a;
    asm("{ .reg .u64 t; cvta.to.shared.u64 t, %1; cvt.u32.u64 %0, t; }" : "=r"(a) : "l"(p));
    return a;
}
__device__ __forceinline__ void cp16(uint32_t dst, const void* src) {
    asm volatile("cp.async.cg.shared.global [%0], [%1], 16;" :: "r"(dst), "l"(src));
}
__device__ __forceinline__ void ldsm4(uint32_t* r, uint32_t addr) {
    asm volatile("ldmatrix.sync.aligned.m8n8.x4.shared.b16 {%0,%1,%2,%3}, [%4];"
        : "=r"(r[0]), "=r"(r[1]), "=r"(r[2]), "=r"(r[3]) : "r"(addr));
}
__device__ __forceinline__ void mma_fp16(float* c, const uint32_t* a, const uint32_t* b) {
    asm volatile("mma.sync.aligned.m16n8k16.row.col.f32.f16.f16.f32 "
        "{%0,%1,%2,%3}, {%4,%5,%6,%7}, {%8,%9}, {%0,%1,%2,%3};"
        : "+f"(c[0]), "+f"(c[1]), "+f"(c[2]), "+f"(c[3])
        : "r"(a[0]), "r"(a[1]), "r"(a[2]), "r"(a[3]), "r"(b[0]), "r"(b[1]));
}

// ---------------- input projection -> fp16 ----------------
__global__ void input_proj_kernel(const float* __restrict__ pose,
                                  const float* __restrict__ Wp,
                                  const float* __restrict__ bp,
                                  __half* __restrict__ xh) {
    long idx = (long)blockIdx.x * blockDim.x + threadIdx.x;
    if (idx >= (long)T_FR * NN * FF) return;
    int f = (int)(idx % FF);
    long tn = idx / FF;
    const float* p = pose + tn * DIN;
    float v = p[0] * Wp[f] + p[1] * Wp[FF + f] + p[2] * Wp[2 * FF + f] + bp[f];
    xh[idx] = __float2half_rn(v);
}

// ---------------- weight transpose: W [K][N] fp32 -> Wt [N][K] fp16 ----------------
__global__ void wsplit_kernel(const float* __restrict__ W,
                              __half* __restrict__ hi, int K, int N) {
    __shared__ float tile[32][33];
    int b = blockIdx.z;
    const float* Wb = W + (long)b * K * N;
    __half* hb = hi + (long)b * K * N;
    int kb = blockIdx.y * 32, nb = blockIdx.x * 32;
    for (int r = threadIdx.y; r < 32; r += 8)
        tile[r][threadIdx.x] = Wb[(long)(kb + r) * N + nb + threadIdx.x];
    __syncthreads();
    for (int r = threadIdx.y; r < 32; r += 8) {
        float v = tile[threadIdx.x][r];
        long o = (long)(nb + r) * K + kb + threadIdx.x;
        hb[o] = __float2half_rn(v);
    }
}

// ---------------- adjacency -> padded neighbor lists ----------------
__global__ void adjlist_kernel(const int* __restrict__ adj,
                               int* __restrict__ nnz, int* __restrict__ cols) {
    __shared__ int cnt;
    int i = blockIdx.x;
    if (threadIdx.x == 0) cnt = 0;
    __syncthreads();
    for (int j = threadIdx.x; j < NN; j += blockDim.x) {
        if (adj[(long)i * NN + j] > 0) {
            int p = atomicAdd(&cnt, 1);
            if (p < MAXN) cols[i * MAXN + p] = j;
        }
    }
    __syncthreads();
    if (threadIdx.x == 0) nnz[i] = (cnt < MAXN) ? cnt : MAXN;
}

// ---------------- zero f/g accumulators ----------------
__global__ void zero_fg_kernel(float* __restrict__ f, float* __restrict__ g, int n) {
    int i = blockIdx.x * blockDim.x + threadIdx.x;
    if (i < n) { f[i] = 0.f; g[i] = 0.f; }
}

// ============================================================================
// fp16 1-pass tensor-core GEMM: C(fp16) = Ah @ Bh^T, fused f/g epilogue (fp32).
// CTA tile 128x64, warp tile 32x32 (8 warps = 4M x 2N), BK=32,
// 3-stage cp.async, 1 sync/iter. (Round-14 skeleton; only C dtype changed.)
// ============================================================================
#define BOF 5120                 // B rows start at 128*40 halfs
#define STG 7680                 // 192 * 40 halfs
#define GEMM_SMEM (3 * STG * 2)  // 46080 bytes

__global__ __launch_bounds__(256, 3)
void gemm_tc(const __half* __restrict__ Ah, const __half* __restrict__ Bh,
             __half* __restrict__ C,
             int K, int lda, int ldb, int ldc,
             long aStride, int aDiv, long bStride, int bMod,
             long cOuter, int cDiv, long cInner, int epi,
             float* __restrict__ fOut, float* __restrict__ gOut,
             const float* __restrict__ aVec, int aMod, int fgEnable) {
    extern __shared__ __align__(16) unsigned short smg[];
    uint32_t sb = smem_u32(smg);

    int tid = threadIdx.x;
    int lane = tid & 31;
    int warp = tid >> 5;
    int wm = warp >> 1;        // 0..3 -> rows wm*32
    int wn = warp & 1;         // 0..1 -> cols wn*32
    int g = lane >> 2;
    int q = lane & 3;

    int b = blockIdx.z;
    int col0 = blockIdx.x * 64;
    int row0 = blockIdx.y * 128;
    const __half* AhB = Ah + (long)(b / aDiv) * aStride;
    const __half* BhB = Bh + (long)(b % bMod) * bStride;
    __half* Cb = C + (long)(b / cDiv) * cOuter + (long)(b % cDiv) * cInner;

    float acc[2][4][4];
    #pragma unroll
    for (int i = 0; i < 2; i++)
        #pragma unroll
        for (int j = 0; j < 4; j++)
            #pragma unroll
            for (int k = 0; k < 4; k++) acc[i][j][k] = 0.f;

    int aRowA = (lane & 15);
    int kHalf = (lane >> 4) << 3;

    auto issue_stage = [&](int k0, int st) {
        uint32_t base = sb + (uint32_t)(st * STG * 2);
        #pragma unroll
        for (int it = 0; it < 3; it++) {
            int idx = tid + it * 256;       // 0..767
            int r = idx >> 2;               // 0..191
            int seg = idx & 3;
            uint32_t d = base + (uint32_t)((r * 40 + seg * 8) * 2);
            if (r < 128) {
                cp16(d, AhB + (long)(row0 + r) * lda + k0 + seg * 8);
            } else {
                cp16(d, BhB + (long)(col0 + r - 128) * ldb + k0 + seg * 8);
            }
        }
        asm volatile("cp.async.commit_group;");
    };

    int nIter = K >> 5;
    issue_stage(0, 0);
    issue_stage(32, 1);

    int slot = 0;
    for (int i = 0; i < nIter; i++) {
        if (i < nIter - 1) {
            asm volatile("cp.async.wait_group 1;");
        } else {
            asm volatile("cp.async.wait_group 0;");
        }
        __syncthreads();
        if (i + 2 < nIter) {
            int ws = slot + 2; if (ws >= 3) ws -= 3;
            issue_stage((i + 2) << 5, ws);
        }

        uint32_t stBase = sb + (uint32_t)(slot * STG * 2);
        #pragma unroll
        for (int kk = 0; kk < 32; kk += 16) {
            uint32_t ah[2][4], bf[4][2];
            #pragma unroll
            for (int mt = 0; mt < 2; mt++) {
                uint32_t addr = stBase + (uint32_t)(((wm * 32 + mt * 16 + aRowA) * 40 + kk + kHalf) * 2);
                ldsm4(ah[mt], addr);
            }
            #pragma unroll
            for (int ng = 0; ng < 2; ng++) {
                uint32_t r[4];
                uint32_t addr = stBase + (uint32_t)(((BOF) + (wn * 32 + ng * 16 + aRowA) * 40 + kk + kHalf) * 2);
                ldsm4(r, addr);
                bf[ng * 2 + 0][0] = r[0]; bf[ng * 2 + 0][1] = r[2];
                bf[ng * 2 + 1][0] = r[1]; bf[ng * 2 + 1][1] = r[3];
            }
            #pragma unroll
            for (int mt = 0; mt < 2; mt++)
                #pragma unroll
                for (int nt = 0; nt < 4; nt++) mma_fp16(acc[mt][nt], ah[mt], bf[nt]);
        }
        slot++; if (slot >= 3) slot = 0;
    }

    // ---- epilogue: store C fp16 (+epi), fused f/g partial dots (fp32, pre-rounding) ----
    float facc[4] = {0.f, 0.f, 0.f, 0.f};
    float gacc[4] = {0.f, 0.f, 0.f, 0.f};
    const float* av = fgEnable ? (aVec + (long)(b % aMod) * (2 * FF)) : (const float*)0;

    #pragma unroll
    for (int mt = 0; mt < 2; mt++) {
        #pragma unroll
        for (int nt = 0; nt < 4; nt++) {
            int r = row0 + wm * 32 + mt * 16 + g;
            int c = col0 + wn * 32 + nt * 8 + 2 * q;
            float v0 = acc[mt][nt][0], v1 = acc[mt][nt][1];
            float v2 = acc[mt][nt][2], v3 = acc[mt][nt][3];
            if (fgEnable) {
                float a10 = av[c], a11 = av[c + 1];
                float a20 = av[FF + c], a21 = av[FF + c + 1];
                facc[mt * 2 + 0] += v0 * a10 + v1 * a11;
                gacc[mt * 2 + 0] += v0 * a20 + v1 * a21;
                facc[mt * 2 + 1] += v2 * a10 + v3 * a11;
                gacc[mt * 2 + 1] += v2 * a20 + v3 * a21;
            }
            float vv[4] = {v0, v1, v2, v3};
            #pragma unroll
            for (int j = 0; j < 4; j++) {
                float u = vv[j];
                if (epi >= 1) u = (u >= 0.f) ? u : expm1f(u);
                if (epi == 2) u = (u >= 0.f) ? u : expm1f(u);
                vv[j] = u;
            }
            *(__half2*)&Cb[(long)r * ldc + c] = __floats2half2_rn(vv[0], vv[1]);
            *(__half2*)&Cb[(long)(r + 8) * ldc + c] = __floats2half2_rn(vv[2], vv[3]);
        }
    }
    if (fgEnable) {
        #pragma unroll
        for (int idx = 0; idx < 4; idx++) {
            facc[idx] += __shfl_xor_sync(0xffffffffu, facc[idx], 1);
            facc[idx] += __shfl_xor_sync(0xffffffffu, facc[idx], 2);
            gacc[idx] += __shfl_xor_sync(0xffffffffu, gacc[idx], 1);
            gacc[idx] += __shfl_xor_sync(0xffffffffu, gacc[idx], 2);
        }
        if (q == 0) {
            #pragma unroll
            for (int mt = 0; mt < 2; mt++) {
                #pragma unroll
                for (int s = 0; s < 2; s++) {
                    int row = row0 + wm * 32 + mt * 16 + g + s * 8;
                    long w = (long)b * NN + row;
                    atomicAdd(&fOut[w], facc[mt * 2 + s]);
                    atomicAdd(&gOut[w], gacc[mt * 2 + s]);
                }
            }
        }
    }
}

// ---------------- sparse softmax over neighbor lists ----------------
__global__ void softmax_sparse_kernel(const float* __restrict__ f, const float* __restrict__ g,
                                      const int* __restrict__ nnz, const int* __restrict__ cols,
                                      float* __restrict__ Pc, int totalRows) {
    int w = (int)(((long)blockIdx.x * blockDim.x + threadIdx.x) >> 5);
    int lane = threadIdx.x & 31;
    if (w >= totalRows) return;
    int b = w >> 9;
    int i = w & 511;
    float fi = f[w];
    const float* gb = g + (long)b * NN;
    int n = nnz[i];
    const int* crow = cols + i * MAXN;
    int nc = (n + 31) >> 5;

    float e[4];
    float mx = -INFINITY;
    for (int c = 0; c < nc; c++) {
        int k = c * 32 + lane;
        float v = -INFINITY;
        if (k < n) {
            float xv = fi + gb[crow[k]];
            v = (xv >= 0.f) ? xv : 0.2f * xv;
        }
        e[c] = v;
        mx = fmaxf(mx, v);
    }
    #pragma unroll
    for (int o = 16; o > 0; o >>= 1) mx = fmaxf(mx, __shfl_xor_sync(0xffffffffu, mx, o));

    float s = 0.f;
    for (int c = 0; c < nc; c++) {
        float ev = (e[c] > -1e30f) ? __expf(e[c] - mx) : 0.f;
        e[c] = ev; s += ev;
    }
    #pragma unroll
    for (int o = 16; o > 0; o >>= 1) s += __shfl_xor_sync(0xffffffffu, s, o);
    float inv = 1.0f / s;

    float* prow = Pc + (long)w * MAXN;
    for (int c = 0; c < nc; c++) {
        int k = c * 32 + lane;
        if (k < n) prow[k] = e[c] * inv;
    }
}

// ---------------- sparse attention apply; fp16 Wh staged to fp32 smem ----------------
__global__ __launch_bounds__(256)
void spmm_kernel(const float* __restrict__ Pc, const __half* __restrict__ Wh,
                 const int* __restrict__ nnz, const int* __restrict__ cols,
                 __half* __restrict__ Chi,
                 float* __restrict__ Cf, int writeF,
                 long whStride, long cOuter, int cDiv, long cInner, int ldc, int epi) {
    extern __shared__ float WhS[];     // [NN][SCH] fp32
    int b = blockIdx.y;
    int c0 = blockIdx.x * SCH;
    const __half* Whb = Wh + (long)b * whStride;
    long cOff = (long)(b / cDiv) * cOuter + (long)(b % cDiv) * cInner;

    // stage: read fp16, convert to fp32 in smem. 512*32/8 = 2048 uint4 units.
    for (int idx = threadIdx.x; idx < NN * (SCH / 8); idx += 256) {
        int row = idx >> 2;
        int col8 = (idx & 3) << 3;
        uint4 v = *(const uint4*)(Whb + (long)row * FF + c0 + col8);
        const __half2* hp = (const __half2*)&v;
        float* ws = &WhS[row * SCH + col8];
        #pragma unroll
        for (int t = 0; t < 4; t++) {
            float2 f2 = __half22float2(hp[t]);
            ws[2 * t] = f2.x; ws[2 * t + 1] = f2.y;
        }
    }
    __syncthreads();

    int warp = threadIdx.x >> 5;
    int lane = threadIdx.x & 31;
    for (int i = warp; i < NN; i += 8) {
        int n = nnz[i];
        const int* crow = cols + i * MAXN;
        const float* prow = Pc + ((long)b * NN + i) * MAXN;
        float a0 = 0.f, a1 = 0.f;
        int k = 0;
        for (; k + 2 <= n; k += 2) {
            int j0 = crow[k], j1 = crow[k + 1];
            float w0 = prow[k], w1 = prow[k + 1];
            a0 += w0 * WhS[j0 * SCH + lane];
            a1 += w1 * WhS[j1 * SCH + lane];
        }
        if (k < n) a0 += prow[k] * WhS[crow[k] * SCH + lane];
        float a = a0 + a1;
        if (epi >= 1) a = (a >= 0.f) ? a : expm1f(a);
        if (epi == 2) a = (a >= 0.f) ? a : expm1f(a);
        long o = cOff + (long)i * ldc + c0 + lane;
        Chi[o] = __float2half_rn(a);
        if (writeF) Cf[o] = a;
    }
}

// ---------------- final pool ----------------
__global__ void pool_kernel(const float* __restrict__ x, const float* __restrict__ Wo,
                            const float* __restrict__ bo, float* __restrict__ out) {
    int t = blockIdx.x;
    int f = threadIdx.x;
    __shared__ float m[FF];
    const float* xt = x + (long)t * NN * FF;
    float s = 0.f;
    for (int n = 0; n < NN; n++) s += xt[n * FF + f];
    m[f] = s * (1.0f / NN);
    __syncthreads();
    float o = bo[f];
    for (int k = 0; k < FF; k++) o += m[k] * Wo[k * FF + f];
    out[t * FF + f] = o;
}

// ---------------- host orchestration ----------------
extern "C" void kernel_launch(void* const* d_in, const int* in_sizes, int n_in,
                              void* d_out, int out_size) {
    const float* pose    = (const float*)d_in[0];
    const int*   adj     = (const int*)  d_in[1];
    const float* Wp      = (const float*)d_in[2];
    const float* bp      = (const float*)d_in[3];
    const float* W_heads = (const float*)d_in[4];
    const float* a_heads = (const float*)d_in[5];
    const float* W_out   = (const float*)d_in[6];
    const float* a_out   = (const float*)d_in[7];
    const float* Wo      = (const float*)d_in[8];
    const float* bo      = (const float*)d_in[9];
    float* out = (float*)d_out;

    float *x, *fb, *gb, *P;
    __half *Whh, *xh, *xch, *Wth, *Woth;
    int *nnz, *colsArr;
    cudaGetSymbolAddress((void**)&x,    g_x);
    cudaGetSymbolAddress((void**)&Whh,  g_Whh);
    cudaGetSymbolAddress((void**)&xh,   g_xh);
    cudaGetSymbolAddress((void**)&xch,  g_xch);
    cudaGetSymbolAddress((void**)&Wth,  g_Wth);
    cudaGetSymbolAddress((void**)&Woth, g_Woth);
    cudaGetSymbolAddress((void**)&fb,   g_f);
    cudaGetSymbolAddress((void**)&gb,   g_g);
    cudaGetSymbolAddress((void**)&P,    g_P);
    cudaGetSymbolAddress((void**)&nnz,  g_nnz);
    cudaGetSymbolAddress((void**)&colsArr, g_cols);

    static bool attrSet = false;
    if (!attrSet) {
        cudaFuncSetAttribute(spmm_kernel,
                             cudaFuncAttributeMaxDynamicSharedMemorySize, NN * SCH * 4);
        cudaFuncSetAttribute(gemm_tc,
                             cudaFuncAttributeMaxDynamicSharedMemorySize, GEMM_SMEM);
        attrSet = true;
    }

    adjlist_kernel<<<NN, 256>>>(adj, nnz, colsArr);

    {
        dim3 blk(32, 8);
        dim3 gh(FF / 32, FF / 32, LL * HH);
        wsplit_kernel<<<gh, blk>>>(W_heads, Wth, FF, FF);
        dim3 go(FF / 32, (HH * FF) / 32, LL);
        wsplit_kernel<<<go, blk>>>(W_out, Woth, HH * FF, FF);
    }

    {
        long total = (long)T_FR * NN * FF;
        input_proj_kernel<<<(unsigned)((total + 255) / 256), 256>>>(pose, Wp, bp, xh);
    }

    for (int l = 0; l < LL; l++) {
        const __half* Wlh = Wth  + (long)l * HH * FF * FF;
        const __half* Woh = Woth + (long)l * FF * HH * FF;
        const float* al  = a_heads + (long)l * HH * 2 * FF;
        const float* aol = a_out   + (long)l * 2 * FF;

        // 2a. Wh(fp16) = x @ W_heads  (fused f/g)
        zero_fg_kernel<<<(T_FR * HH * NN + 255) / 256, 256>>>(fb, gb, T_FR * HH * NN);
        {
            dim3 grid(FF / 64, NN / 128, T_FR * HH);
            gemm_tc<<<grid, 256, GEMM_SMEM>>>(xh, Wlh, Whh,
                FF, FF, FF, FF,
                (long)NN * FF, HH,
                (long)FF * FF, HH,
                (long)NN * FF, 1, 0,
                0, fb, gb, al, HH, 1);
        }
        // 2c. sparse softmax -> compact P
        {
            int rows = T_FR * HH * NN;
            softmax_sparse_kernel<<<(rows * 32 + 255) / 256, 256>>>(fb, gb, nnz, colsArr, P, rows);
        }
        // 2d. xcat = elu(P @ Wh) -> fp16
        {
            dim3 grid(FF / SCH, T_FR * HH);
            spmm_kernel<<<grid, 256, NN * SCH * 4>>>(P, Whh, nnz, colsArr,
                xch, (float*)0, 0,
                (long)NN * FF,
                (long)NN * HH * FF, HH, FF, HH * FF, 1);
        }
        // 2e. Whout(fp16) = xcat @ W_out  (K=2048, fused f/g)
        zero_fg_kernel<<<(T_FR * NN + 255) / 256, 256>>>(fb, gb, T_FR * NN);
        {
            dim3 grid(FF / 64, NN / 128, T_FR);
            gemm_tc<<<grid, 256, GEMM_SMEM>>>(xch, Woh, Whh,
                HH * FF, HH * FF, HH * FF, FF,
                (long)NN * HH * FF, 1,
                0, 1,
                (long)NN * FF, 1, 0,
                0, fb, gb, aol, 1, 1);
        }
        // 2g. sparse softmax -> compact P
        {
            int rows = T_FR * NN;
            softmax_sparse_kernel<<<(rows * 32 + 255) / 256, 256>>>(fb, gb, nnz, colsArr, P, rows);
        }
        // 2h. x = elu(elu(P @ Whout)) -> fp16 (+ fp32 last layer)
        {
            dim3 grid(FF / SCH, T_FR);
            spmm_kernel<<<grid, 256, NN * SCH * 4>>>(P, Whh, nnz, colsArr,
                xh, x, (l == LL - 1) ? 1 : 0,
                (long)NN * FF,
                (long)NN * FF, 1, 0, FF, 2);
        }
    }

    pool_kernel<<<T_FR, 256>>>(x, Wo, bo, out);
}

// round 16
// speedup vs baseline: 1.4852x; 1.1679x over previous
#include <cuda_runtime.h>
#include <cuda_fp16.h>
#include <math.h>
#include <stdint.h>

// Problem constants
#define T_FR 32
#define NN 512
#define FF 256
#define HH 8
#define LL 3
#define DIN 3
#define MAXN 128
#define SCH 64   // spmm column chunk (fp16 smem staging)

// ---------------- scratch (device globals; allocation-free rule) ----------------
__device__ float  g_x[T_FR * NN * FF];
__device__ __half g_Whh[T_FR * HH * NN * FF];   // fp16 Wh intermediate
__device__ __half g_xh[T_FR * NN * FF];
__device__ __half g_xch[T_FR * NN * HH * FF];
__device__ __half g_Wth[LL * HH * FF * FF];     // W_heads^T [l][h][n][k] fp16
__device__ __half g_Woth[LL * FF * HH * FF];    // W_out^T   [l][n][k]    fp16
__device__ float  g_f[T_FR * HH * NN];
__device__ float  g_g[T_FR * HH * NN];
__device__ float  g_P[(long)T_FR * HH * NN * MAXN];
__device__ int    g_nnz[NN];
__device__ int    g_cols[NN * MAXN];

// ---------------- helpers ----------------
__device__ __forceinline__ uint32_t smem_u32(const void* p) {
    uint32_t a;
    asm("{ .reg .u64 t; cvta.to.shared.u64 t, %1; cvt.u32.u64 %0, t; }" : "=r"(a) : "l"(p));
    return a;
}
__device__ __forceinline__ void cp16(uint32_t dst, const void* src) {
    asm volatile("cp.async.cg.shared.global [%0], [%1], 16;" :: "r"(dst), "l"(src));
}
__device__ __forceinline__ void ldsm4(uint32_t* r, uint32_t addr) {
    asm volatile("ldmatrix.sync.aligned.m8n8.x4.shared.b16 {%0,%1,%2,%3}, [%4];"
        : "=r"(r[0]), "=r"(r[1]), "=r"(r[2]), "=r"(r[3]) : "r"(addr));
}
__device__ __forceinline__ void mma_fp16(float* c, const uint32_t* a, const uint32_t* b) {
    asm volatile("mma.sync.aligned.m16n8k16.row.col.f32.f16.f16.f32 "
        "{%0,%1,%2,%3}, {%4,%5,%6,%7}, {%8,%9}, {%0,%1,%2,%3};"
        : "+f"(c[0]), "+f"(c[1]), "+f"(c[2]), "+f"(c[3])
        : "r"(a[0]), "r"(a[1]), "r"(a[2]), "r"(a[3]), "r"(b[0]), "r"(b[1]));
}

// ---------------- input projection -> fp16 ----------------
__global__ void input_proj_kernel(const float* __restrict__ pose,
                                  const float* __restrict__ Wp,
                                  const float* __restrict__ bp,
                                  __half* __restrict__ xh) {
    long idx = (long)blockIdx.x * blockDim.x + threadIdx.x;
    if (idx >= (long)T_FR * NN * FF) return;
    int f = (int)(idx % FF);
    long tn = idx / FF;
    const float* p = pose + tn * DIN;
    float v = p[0] * Wp[f] + p[1] * Wp[FF + f] + p[2] * Wp[2 * FF + f] + bp[f];
    xh[idx] = __float2half_rn(v);
}

// ---------------- weight transpose: W [K][N] fp32 -> Wt [N][K] fp16 ----------------
__global__ void wsplit_kernel(const float* __restrict__ W,
                              __half* __restrict__ hi, int K, int N) {
    __shared__ float tile[32][33];
    int b = blockIdx.z;
    const float* Wb = W + (long)b * K * N;
    __half* hb = hi + (long)b * K * N;
    int kb = blockIdx.y * 32, nb = blockIdx.x * 32;
    for (int r = threadIdx.y; r < 32; r += 8)
        tile[r][threadIdx.x] = Wb[(long)(kb + r) * N + nb + threadIdx.x];
    __syncthreads();
    for (int r = threadIdx.y; r < 32; r += 8) {
        float v = tile[threadIdx.x][r];
        long o = (long)(nb + r) * K + kb + threadIdx.x;
        hb[o] = __float2half_rn(v);
    }
}

// ---------------- adjacency -> padded neighbor lists ----------------
__global__ void adjlist_kernel(const int* __restrict__ adj,
                               int* __restrict__ nnz, int* __restrict__ cols) {
    __shared__ int cnt;
    int i = blockIdx.x;
    if (threadIdx.x == 0) cnt = 0;
    __syncthreads();
    for (int j = threadIdx.x; j < NN; j += blockDim.x) {
        if (adj[(long)i * NN + j] > 0) {
            int p = atomicAdd(&cnt, 1);
            if (p < MAXN) cols[i * MAXN + p] = j;
        }
    }
    __syncthreads();
    if (threadIdx.x == 0) nnz[i] = (cnt < MAXN) ? cnt : MAXN;
}

// ---------------- zero f/g accumulators ----------------
__global__ void zero_fg_kernel(float* __restrict__ f, float* __restrict__ g, int n) {
    int i = blockIdx.x * blockDim.x + threadIdx.x;
    if (i < n) { f[i] = 0.f; g[i] = 0.f; }
}

// ============================================================================
// fp16 1-pass tensor-core GEMM: C(fp16) = Ah @ Bh^T, fused f/g epilogue (fp32).
// CTA tile 128x64, warp tile 32x32 (8 warps = 4M x 2N), BK=32,
// 3-stage cp.async, 1 sync/iter. (Proven round-14/15 skeleton.)
// ============================================================================
#define BOF 5120                 // B rows start at 128*40 halfs
#define STG 7680                 // 192 * 40 halfs
#define GEMM_SMEM (3 * STG * 2)  // 46080 bytes

__global__ __launch_bounds__(256, 3)
void gemm_tc(const __half* __restrict__ Ah, const __half* __restrict__ Bh,
             __half* __restrict__ C,
             int K, int lda, int ldb, int ldc,
             long aStride, int aDiv, long bStride, int bMod,
             long cOuter, int cDiv, long cInner, int epi,
             float* __restrict__ fOut, float* __restrict__ gOut,
             const float* __restrict__ aVec, int aMod, int fgEnable) {
    extern __shared__ __align__(16) unsigned short smg[];
    uint32_t sb = smem_u32(smg);

    int tid = threadIdx.x;
    int lane = tid & 31;
    int warp = tid >> 5;
    int wm = warp >> 1;        // 0..3 -> rows wm*32
    int wn = warp & 1;         // 0..1 -> cols wn*32
    int g = lane >> 2;
    int q = lane & 3;

    int b = blockIdx.z;
    int col0 = blockIdx.x * 64;
    int row0 = blockIdx.y * 128;
    const __half* AhB = Ah + (long)(b / aDiv) * aStride;
    const __half* BhB = Bh + (long)(b % bMod) * bStride;
    __half* Cb = C + (long)(b / cDiv) * cOuter + (long)(b % cDiv) * cInner;

    float acc[2][4][4];
    #pragma unroll
    for (int i = 0; i < 2; i++)
        #pragma unroll
        for (int j = 0; j < 4; j++)
            #pragma unroll
            for (int k = 0; k < 4; k++) acc[i][j][k] = 0.f;

    int aRowA = (lane & 15);
    int kHalf = (lane >> 4) << 3;

    auto issue_stage = [&](int k0, int st) {
        uint32_t base = sb + (uint32_t)(st * STG * 2);
        #pragma unroll
        for (int it = 0; it < 3; it++) {
            int idx = tid + it * 256;       // 0..767
            int r = idx >> 2;               // 0..191
            int seg = idx & 3;
            uint32_t d = base + (uint32_t)((r * 40 + seg * 8) * 2);
            if (r < 128) {
                cp16(d, AhB + (long)(row0 + r) * lda + k0 + seg * 8);
            } else {
                cp16(d, BhB + (long)(col0 + r - 128) * ldb + k0 + seg * 8);
            }
        }
        asm volatile("cp.async.commit_group;");
    };

    int nIter = K >> 5;
    issue_stage(0, 0);
    issue_stage(32, 1);

    int slot = 0;
    for (int i = 0; i < nIter; i++) {
        if (i < nIter - 1) {
            asm volatile("cp.async.wait_group 1;");
        } else {
            asm volatile("cp.async.wait_group 0;");
        }
        __syncthreads();
        if (i + 2 < nIter) {
            int ws = slot + 2; if (ws >= 3) ws -= 3;
            issue_stage((i + 2) << 5, ws);
        }

        uint32_t stBase = sb + (uint32_t)(slot * STG * 2);
        #pragma unroll
        for (int kk = 0; kk < 32; kk += 16) {
            uint32_t ah[2][4], bf[4][2];
            #pragma unroll
            for (int mt = 0; mt < 2; mt++) {
                uint32_t addr = stBase + (uint32_t)(((wm * 32 + mt * 16 + aRowA) * 40 + kk + kHalf) * 2);
                ldsm4(ah[mt], addr);
            }
            #pragma unroll
            for (int ng = 0; ng < 2; ng++) {
                uint32_t r[4];
                uint32_t addr = stBase + (uint32_t)(((BOF) + (wn * 32 + ng * 16 + aRowA) * 40 + kk + kHalf) * 2);
                ldsm4(r, addr);
                bf[ng * 2 + 0][0] = r[0]; bf[ng * 2 + 0][1] = r[2];
                bf[ng * 2 + 1][0] = r[1]; bf[ng * 2 + 1][1] = r[3];
            }
            #pragma unroll
            for (int mt = 0; mt < 2; mt++)
                #pragma unroll
                for (int nt = 0; nt < 4; nt++) mma_fp16(acc[mt][nt], ah[mt], bf[nt]);
        }
        slot++; if (slot >= 3) slot = 0;
    }

    // ---- epilogue: store C fp16 (+epi), fused f/g partial dots (fp32, pre-rounding) ----
    float facc[4] = {0.f, 0.f, 0.f, 0.f};
    float gacc[4] = {0.f, 0.f, 0.f, 0.f};
    const float* av = fgEnable ? (aVec + (long)(b % aMod) * (2 * FF)) : (const float*)0;

    #pragma unroll
    for (int mt = 0; mt < 2; mt++) {
        #pragma unroll
        for (int nt = 0; nt < 4; nt++) {
            int r = row0 + wm * 32 + mt * 16 + g;
            int c = col0 + wn * 32 + nt * 8 + 2 * q;
            float v0 = acc[mt][nt][0], v1 = acc[mt][nt][1];
            float v2 = acc[mt][nt][2], v3 = acc[mt][nt][3];
            if (fgEnable) {
                float a10 = av[c], a11 = av[c + 1];
                float a20 = av[FF + c], a21 = av[FF + c + 1];
                facc[mt * 2 + 0] += v0 * a10 + v1 * a11;
                gacc[mt * 2 + 0] += v0 * a20 + v1 * a21;
                facc[mt * 2 + 1] += v2 * a10 + v3 * a11;
                gacc[mt * 2 + 1] += v2 * a20 + v3 * a21;
            }
            float vv[4] = {v0, v1, v2, v3};
            #pragma unroll
            for (int j = 0; j < 4; j++) {
                float u = vv[j];
                if (epi >= 1) u = (u >= 0.f) ? u : expm1f(u);
                if (epi == 2) u = (u >= 0.f) ? u : expm1f(u);
                vv[j] = u;
            }
            *(__half2*)&Cb[(long)r * ldc + c] = __floats2half2_rn(vv[0], vv[1]);
            *(__half2*)&Cb[(long)(r + 8) * ldc + c] = __floats2half2_rn(vv[2], vv[3]);
        }
    }
    if (fgEnable) {
        #pragma unroll
        for (int idx = 0; idx < 4; idx++) {
            facc[idx] += __shfl_xor_sync(0xffffffffu, facc[idx], 1);
            facc[idx] += __shfl_xor_sync(0xffffffffu, facc[idx], 2);
            gacc[idx] += __shfl_xor_sync(0xffffffffu, gacc[idx], 1);
            gacc[idx] += __shfl_xor_sync(0xffffffffu, gacc[idx], 2);
        }
        if (q == 0) {
            #pragma unroll
            for (int mt = 0; mt < 2; mt++) {
                #pragma unroll
                for (int s = 0; s < 2; s++) {
                    int row = row0 + wm * 32 + mt * 16 + g + s * 8;
                    long w = (long)b * NN + row;
                    atomicAdd(&fOut[w], facc[mt * 2 + s]);
                    atomicAdd(&gOut[w], gacc[mt * 2 + s]);
                }
            }
        }
    }
}

// ---------------- sparse softmax over neighbor lists ----------------
__global__ void softmax_sparse_kernel(const float* __restrict__ f, const float* __restrict__ g,
                                      const int* __restrict__ nnz, const int* __restrict__ cols,
                                      float* __restrict__ Pc, int totalRows) {
    int w = (int)(((long)blockIdx.x * blockDim.x + threadIdx.x) >> 5);
    int lane = threadIdx.x & 31;
    if (w >= totalRows) return;
    int b = w >> 9;
    int i = w & 511;
    float fi = f[w];
    const float* gb = g + (long)b * NN;
    int n = nnz[i];
    const int* crow = cols + i * MAXN;
    int nc = (n + 31) >> 5;

    float e[4];
    float mx = -INFINITY;
    for (int c = 0; c < nc; c++) {
        int k = c * 32 + lane;
        float v = -INFINITY;
        if (k < n) {
            float xv = fi + gb[crow[k]];
            v = (xv >= 0.f) ? xv : 0.2f * xv;
        }
        e[c] = v;
        mx = fmaxf(mx, v);
    }
    #pragma unroll
    for (int o = 16; o > 0; o >>= 1) mx = fmaxf(mx, __shfl_xor_sync(0xffffffffu, mx, o));

    float s = 0.f;
    for (int c = 0; c < nc; c++) {
        float ev = (e[c] > -1e30f) ? __expf(e[c] - mx) : 0.f;
        e[c] = ev; s += ev;
    }
    #pragma unroll
    for (int o = 16; o > 0; o >>= 1) s += __shfl_xor_sync(0xffffffffu, s, o);
    float inv = 1.0f / s;

    float* prow = Pc + (long)w * MAXN;
    for (int c = 0; c < nc; c++) {
        int k = c * 32 + lane;
        if (k < n) prow[k] = e[c] * inv;
    }
}

// ---------------- sparse attention apply; SCH=64, fp16 smem staging ----------------
__global__ __launch_bounds__(256)
void spmm_kernel(const float* __restrict__ Pc, const __half* __restrict__ Wh,
                 const int* __restrict__ nnz, const int* __restrict__ cols,
                 __half* __restrict__ Chi,
                 float* __restrict__ Cf, int writeF,
                 long whStride, long cOuter, int cDiv, long cInner, int ldc, int epi) {
    extern __shared__ __half2 WhS2[];  // [NN][SCH/2] half2
    int b = blockIdx.y;
    int c0 = blockIdx.x * SCH;
    const __half* Whb = Wh + (long)b * whStride;
    long cOff = (long)(b / cDiv) * cOuter + (long)(b % cDiv) * cInner;

    // stage fp16 Wh rows (lossless copy): 512*64 halves = 4096 uint4
    for (int idx = threadIdx.x; idx < NN * (SCH / 8); idx += 256) {
        int row = idx >> 3;
        int col8 = (idx & 7) << 3;
        uint4 v = *(const uint4*)(Whb + (long)row * FF + c0 + col8);
        *(uint4*)&WhS2[row * (SCH / 2) + (col8 >> 1)] = v;
    }
    __syncthreads();

    int warp = threadIdx.x >> 5;
    int lane = threadIdx.x & 31;
    for (int i = warp; i < NN; i += 8) {
        int n = nnz[i];
        const int* crow = cols + i * MAXN;
        const float* prow = Pc + ((long)b * NN + i) * MAXN;
        // even/odd-k accumulator split (matches prior numerics), 2 cols per lane
        float e0 = 0.f, e1 = 0.f, o0 = 0.f, o1 = 0.f;
        int k = 0;
        for (; k + 2 <= n; k += 2) {
            int j0 = crow[k], j1 = crow[k + 1];
            float w0 = prow[k], w1 = prow[k + 1];
            float2 v0 = __half22float2(WhS2[j0 * (SCH / 2) + lane]);
            float2 v1 = __half22float2(WhS2[j1 * (SCH / 2) + lane]);
            e0 += w0 * v0.x; e1 += w0 * v0.y;
            o0 += w1 * v1.x; o1 += w1 * v1.y;
        }
        if (k < n) {
            float w0 = prow[k];
            float2 v0 = __half22float2(WhS2[crow[k] * (SCH / 2) + lane]);
            e0 += w0 * v0.x; e1 += w0 * v0.y;
        }
        float ax = e0 + o0, ay = e1 + o1;
        if (epi >= 1) { ax = (ax >= 0.f) ? ax : expm1f(ax); ay = (ay >= 0.f) ? ay : expm1f(ay); }
        if (epi == 2) { ax = (ax >= 0.f) ? ax : expm1f(ax); ay = (ay >= 0.f) ? ay : expm1f(ay); }
        long o = cOff + (long)i * ldc + c0 + 2 * lane;
        *(__half2*)&Chi[o] = __floats2half2_rn(ax, ay);
        if (writeF) *(float2*)&Cf[o] = make_float2(ax, ay);
    }
}

// ---------------- final pool ----------------
__global__ void pool_kernel(const float* __restrict__ x, const float* __restrict__ Wo,
                            const float* __restrict__ bo, float* __restrict__ out) {
    int t = blockIdx.x;
    int f = threadIdx.x;
    __shared__ float m[FF];
    const float* xt = x + (long)t * NN * FF;
    float s = 0.f;
    for (int n = 0; n < NN; n++) s += xt[n * FF + f];
    m[f] = s * (1.0f / NN);
    __syncthreads();
    float o = bo[f];
    for (int k = 0; k < FF; k++) o += m[k] * Wo[k * FF + f];
    out[t * FF + f] = o;
}

// ---------------- host orchestration ----------------
extern "C" void kernel_launch(void* const* d_in, const int* in_sizes, int n_in,
                              void* d_out, int out_size) {
    const float* pose    = (const float*)d_in[0];
    const int*   adj     = (const int*)  d_in[1];
    const float* Wp      = (const float*)d_in[2];
    const float* bp      = (const float*)d_in[3];
    const float* W_heads = (const float*)d_in[4];
    const float* a_heads = (const float*)d_in[5];
    const float* W_out   = (const float*)d_in[6];
    const float* a_out   = (const float*)d_in[7];
    const float* Wo      = (const float*)d_in[8];
    const float* bo      = (const float*)d_in[9];
    float* out = (float*)d_out;

    float *x, *fb, *gb, *P;
    __half *Whh, *xh, *xch, *Wth, *Woth;
    int *nnz, *colsArr;
    cudaGetSymbolAddress((void**)&x,    g_x);
    cudaGetSymbolAddress((void**)&Whh,  g_Whh);
    cudaGetSymbolAddress((void**)&xh,   g_xh);
    cudaGetSymbolAddress((void**)&xch,  g_xch);
    cudaGetSymbolAddress((void**)&Wth,  g_Wth);
    cudaGetSymbolAddress((void**)&Woth, g_Woth);
    cudaGetSymbolAddress((void**)&fb,   g_f);
    cudaGetSymbolAddress((void**)&gb,   g_g);
    cudaGetSymbolAddress((void**)&P,    g_P);
    cudaGetSymbolAddress((void**)&nnz,  g_nnz);
    cudaGetSymbolAddress((void**)&colsArr, g_cols);

    static bool attrSet = false;
    if (!attrSet) {
        cudaFuncSetAttribute(spmm_kernel,
                             cudaFuncAttributeMaxDynamicSharedMemorySize, NN * SCH * 2);
        cudaFuncSetAttribute(gemm_tc,
                             cudaFuncAttributeMaxDynamicSharedMemorySize, GEMM_SMEM);
        attrSet = true;
    }

    adjlist_kernel<<<NN, 256>>>(adj, nnz, colsArr);

    {
        dim3 blk(32, 8);
        dim3 gh(FF / 32, FF / 32, LL * HH);
        wsplit_kernel<<<gh, blk>>>(W_heads, Wth, FF, FF);
        dim3 go(FF / 32, (HH * FF) / 32, LL);
        wsplit_kernel<<<go, blk>>>(W_out, Woth, HH * FF, FF);
    }

    {
        long total = (long)T_FR * NN * FF;
        input_proj_kernel<<<(unsigned)((total + 255) / 256), 256>>>(pose, Wp, bp, xh);
    }

    for (int l = 0; l < LL; l++) {
        const __half* Wlh = Wth  + (long)l * HH * FF * FF;
        const __half* Woh = Woth + (long)l * FF * HH * FF;
        const float* al  = a_heads + (long)l * HH * 2 * FF;
        const float* aol = a_out   + (long)l * 2 * FF;

        // 2a. Wh(fp16) = x @ W_heads  (fused f/g)
        zero_fg_kernel<<<(T_FR * HH * NN + 255) / 256, 256>>>(fb, gb, T_FR * HH * NN);
        {
            dim3 grid(FF / 64, NN / 128, T_FR * HH);
            gemm_tc<<<grid, 256, GEMM_SMEM>>>(xh, Wlh, Whh,
                FF, FF, FF, FF,
                (long)NN * FF, HH,
                (long)FF * FF, HH,
                (long)NN * FF, 1, 0,
                0, fb, gb, al, HH, 1);
        }
        // 2c. sparse softmax -> compact P
        {
            int rows = T_FR * HH * NN;
            softmax_sparse_kernel<<<(rows * 32 + 255) / 256, 256>>>(fb, gb, nnz, colsArr, P, rows);
        }
        // 2d. xcat = elu(P @ Wh) -> fp16  (SCH=64)
        {
            dim3 grid(FF / SCH, T_FR * HH);
            spmm_kernel<<<grid, 256, NN * SCH * 2>>>(P, Whh, nnz, colsArr,
                xch, (float*)0, 0,
                (long)NN * FF,
                (long)NN * HH * FF, HH, FF, HH * FF, 1);
        }
        // 2e. Whout(fp16) = xcat @ W_out  (K=2048, fused f/g)
        zero_fg_kernel<<<(T_FR * NN + 255) / 256, 256>>>(fb, gb, T_FR * NN);
        {
            dim3 grid(FF / 64, NN / 128, T_FR);
            gemm_tc<<<grid, 256, GEMM_SMEM>>>(xch, Woh, Whh,
                HH * FF, HH * FF, HH * FF, FF,
                (long)NN * HH * FF, 1,
                0, 1,
                (long)NN * FF, 1, 0,
                0, fb, gb, aol, 1, 1);
        }
        // 2g. sparse softmax -> compact P
        {
            int rows = T_FR * NN;
            softmax_sparse_kernel<<<(rows * 32 + 255) / 256, 256>>>(fb, gb, nnz, colsArr, P, rows);
        }
        // 2h. x = elu(elu(P @ Whout)) -> fp16 (+ fp32 last layer)
        {
            dim3 grid(FF / SCH, T_FR);
            spmm_kernel<<<grid, 256, NN * SCH * 2>>>(P, Whh, nnz, colsArr,
                xh, x, (l == LL - 1) ? 1 : 0,
                (long)NN * FF,
                (long)NN * FF, 1, 0, FF, 2);
        }
    }

    pool_kernel<<<T_FR, 256>>>(x, Wo, bo, out);
}

// round 17
// speedup vs baseline: 1.4982x; 1.0088x over previous
#include <cuda_runtime.h>
#include <cuda_fp16.h>
#include <math.h>
#include <stdint.h>

// Problem constants
#define T_FR 32
#define NN 512
#define FF 256
#define HH 8
#define LL 3
#define DIN 3
#define MAXN 128
#define SCH 64   // spmm column chunk (fp16 smem staging)

// ---------------- scratch (device globals; allocation-free rule) ----------------
__device__ float  g_x[T_FR * NN * FF];
__device__ __half g_Whh[T_FR * HH * NN * FF];   // fp16 Wh intermediate
__device__ __half g_xh[T_FR * NN * FF];
__device__ __half g_xch[T_FR * NN * HH * FF];
__device__ __half g_Wth[LL * HH * FF * FF];     // W_heads^T [l][h][n][k] fp16
__device__ __half g_Woth[LL * FF * HH * FF];    // W_out^T   [l][n][k]    fp16
__device__ float  g_f[T_FR * HH * NN];
__device__ float  g_g[T_FR * HH * NN];
__device__ __half g_P[(long)T_FR * HH * NN * MAXN];   // fp16 attention probs
__device__ int    g_nnz[NN];
__device__ int    g_cols[NN * MAXN];

// ---------------- helpers ----------------
__device__ __forceinline__ uint32_t smem_u32(const void* p) {
    uint32_t a;
    asm("{ .reg .u64 t; cvta.to.shared.u64 t, %1; cvt.u32.u64 %0, t; }" : "=r"(a) : "l"(p));
    return a;
}
__device__ __forceinline__ void cp16(uint32_t dst, const void* src) {
    asm volatile("cp.async.cg.shared.global [%0], [%1], 16;" :: "r"(dst), "l"(src));
}
__device__ __forceinline__ void ldsm4(uint32_t* r, uint32_t addr) {
    asm volatile("ldmatrix.sync.aligned.m8n8.x4.shared.b16 {%0,%1,%2,%3}, [%4];"
        : "=r"(r[0]), "=r"(r[1]), "=r"(r[2]), "=r"(r[3]) : "r"(addr));
}
__device__ __forceinline__ void mma_fp16(float* c, const uint32_t* a, const uint32_t* b) {
    asm volatile("mma.sync.aligned.m16n8k16.row.col.f32.f16.f16.f32 "
        "{%0,%1,%2,%3}, {%4,%5,%6,%7}, {%8,%9}, {%0,%1,%2,%3};"
        : "+f"(c[0]), "+f"(c[1]), "+f"(c[2]), "+f"(c[3])
        : "r"(a[0]), "r"(a[1]), "r"(a[2]), "r"(a[3]), "r"(b[0]), "r"(b[1]));
}

// ---------------- input projection -> fp16 ----------------
__global__ void input_proj_kernel(const float* __restrict__ pose,
                                  const float* __restrict__ Wp,
                                  const float* __restrict__ bp,
                                  __half* __restrict__ xh) {
    long idx = (long)blockIdx.x * blockDim.x + threadIdx.x;
    if (idx >= (long)T_FR * NN * FF) return;
    int f = (int)(idx % FF);
    long tn = idx / FF;
    const float* p = pose + tn * DIN;
    float v = p[0] * Wp[f] + p[1] * Wp[FF + f] + p[2] * Wp[2 * FF + f] + bp[f];
    xh[idx] = __float2half_rn(v);
}

// ---------------- weight transpose: W [K][N] fp32 -> Wt [N][K] fp16 ----------------
__global__ void wsplit_kernel(const float* __restrict__ W,
                              __half* __restrict__ hi, int K, int N) {
    __shared__ float tile[32][33];
    int b = blockIdx.z;
    const float* Wb = W + (long)b * K * N;
    __half* hb = hi + (long)b * K * N;
    int kb = blockIdx.y * 32, nb = blockIdx.x * 32;
    for (int r = threadIdx.y; r < 32; r += 8)
        tile[r][threadIdx.x] = Wb[(long)(kb + r) * N + nb + threadIdx.x];
    __syncthreads();
    for (int r = threadIdx.y; r < 32; r += 8) {
        float v = tile[threadIdx.x][r];
        long o = (long)(nb + r) * K + kb + threadIdx.x;
        hb[o] = __float2half_rn(v);
    }
}

// ---------------- adjacency -> padded neighbor lists ----------------
__global__ void adjlist_kernel(const int* __restrict__ adj,
                               int* __restrict__ nnz, int* __restrict__ cols) {
    __shared__ int cnt;
    int i = blockIdx.x;
    if (threadIdx.x == 0) cnt = 0;
    __syncthreads();
    for (int j = threadIdx.x; j < NN; j += blockDim.x) {
        if (adj[(long)i * NN + j] > 0) {
            int p = atomicAdd(&cnt, 1);
            if (p < MAXN) cols[i * MAXN + p] = j;
        }
    }
    __syncthreads();
    if (threadIdx.x == 0) nnz[i] = (cnt < MAXN) ? cnt : MAXN;
}

// ---------------- zero f/g accumulators ----------------
__global__ void zero_fg_kernel(float* __restrict__ f, float* __restrict__ g, int n) {
    int i = blockIdx.x * blockDim.x + threadIdx.x;
    if (i < n) { f[i] = 0.f; g[i] = 0.f; }
}

// ============================================================================
// fp16 1-pass tensor-core GEMM: C(fp16) = Ah @ Bh^T, fused f/g epilogue (fp32).
// CTA tile 128x64, warp tile 32x32 (8 warps = 4M x 2N), BK=32,
// 3-stage cp.async, 1 sync/iter. (Proven round-14/15/16 skeleton.)
// ============================================================================
#define BOF 5120                 // B rows start at 128*40 halfs
#define STG 7680                 // 192 * 40 halfs
#define GEMM_SMEM (3 * STG * 2)  // 46080 bytes

__global__ __launch_bounds__(256, 3)
void gemm_tc(const __half* __restrict__ Ah, const __half* __restrict__ Bh,
             __half* __restrict__ C,
             int K, int lda, int ldb, int ldc,
             long aStride, int aDiv, long bStride, int bMod,
             long cOuter, int cDiv, long cInner, int epi,
             float* __restrict__ fOut, float* __restrict__ gOut,
             const float* __restrict__ aVec, int aMod, int fgEnable) {
    extern __shared__ __align__(16) unsigned short smg[];
    uint32_t sb = smem_u32(smg);

    int tid = threadIdx.x;
    int lane = tid & 31;
    int warp = tid >> 5;
    int wm = warp >> 1;        // 0..3 -> rows wm*32
    int wn = warp & 1;         // 0..1 -> cols wn*32
    int g = lane >> 2;
    int q = lane & 3;

    int b = blockIdx.z;
    int col0 = blockIdx.x * 64;
    int row0 = blockIdx.y * 128;
    const __half* AhB = Ah + (long)(b / aDiv) * aStride;
    const __half* BhB = Bh + (long)(b % bMod) * bStride;
    __half* Cb = C + (long)(b / cDiv) * cOuter + (long)(b % cDiv) * cInner;

    float acc[2][4][4];
    #pragma unroll
    for (int i = 0; i < 2; i++)
        #pragma unroll
        for (int j = 0; j < 4; j++)
            #pragma unroll
            for (int k = 0; k < 4; k++) acc[i][j][k] = 0.f;

    int aRowA = (lane & 15);
    int kHalf = (lane >> 4) << 3;

    auto issue_stage = [&](int k0, int st) {
        uint32_t base = sb + (uint32_t)(st * STG * 2);
        #pragma unroll
        for (int it = 0; it < 3; it++) {
            int idx = tid + it * 256;       // 0..767
            int r = idx >> 2;               // 0..191
            int seg = idx & 3;
            uint32_t d = base + (uint32_t)((r * 40 + seg * 8) * 2);
            if (r < 128) {
                cp16(d, AhB + (long)(row0 + r) * lda + k0 + seg * 8);
            } else {
                cp16(d, BhB + (long)(col0 + r - 128) * ldb + k0 + seg * 8);
            }
        }
        asm volatile("cp.async.commit_group;");
    };

    int nIter = K >> 5;
    issue_stage(0, 0);
    issue_stage(32, 1);

    int slot = 0;
    for (int i = 0; i < nIter; i++) {
        if (i < nIter - 1) {
            asm volatile("cp.async.wait_group 1;");
        } else {
            asm volatile("cp.async.wait_group 0;");
        }
        __syncthreads();
        if (i + 2 < nIter) {
            int ws = slot + 2; if (ws >= 3) ws -= 3;
            issue_stage((i + 2) << 5, ws);
        }

        uint32_t stBase = sb + (uint32_t)(slot * STG * 2);
        #pragma unroll
        for (int kk = 0; kk < 32; kk += 16) {
            uint32_t ah[2][4], bf[4][2];
            #pragma unroll
            for (int mt = 0; mt < 2; mt++) {
                uint32_t addr = stBase + (uint32_t)(((wm * 32 + mt * 16 + aRowA) * 40 + kk + kHalf) * 2);
                ldsm4(ah[mt], addr);
            }
            #pragma unroll
            for (int ng = 0; ng < 2; ng++) {
                uint32_t r[4];
                uint32_t addr = stBase + (uint32_t)(((BOF) + (wn * 32 + ng * 16 + aRowA) * 40 + kk + kHalf) * 2);
                ldsm4(r, addr);
                bf[ng * 2 + 0][0] = r[0]; bf[ng * 2 + 0][1] = r[2];
                bf[ng * 2 + 1][0] = r[1]; bf[ng * 2 + 1][1] = r[3];
            }
            #pragma unroll
            for (int mt = 0; mt < 2; mt++)
                #pragma unroll
                for (int nt = 0; nt < 4; nt++) mma_fp16(acc[mt][nt], ah[mt], bf[nt]);
        }
        slot++; if (slot >= 3) slot = 0;
    }

    // ---- epilogue: store C fp16 (+epi), fused f/g partial dots (fp32, pre-rounding) ----
    float facc[4] = {0.f, 0.f, 0.f, 0.f};
    float gacc[4] = {0.f, 0.f, 0.f, 0.f};
    const float* av = fgEnable ? (aVec + (long)(b % aMod) * (2 * FF)) : (const float*)0;

    #pragma unroll
    for (int mt = 0; mt < 2; mt++) {
        #pragma unroll
        for (int nt = 0; nt < 4; nt++) {
            int r = row0 + wm * 32 + mt * 16 + g;
            int c = col0 + wn * 32 + nt * 8 + 2 * q;
            float v0 = acc[mt][nt][0], v1 = acc[mt][nt][1];
            float v2 = acc[mt][nt][2], v3 = acc[mt][nt][3];
            if (fgEnable) {
                float a10 = av[c], a11 = av[c + 1];
                float a20 = av[FF + c], a21 = av[FF + c + 1];
                facc[mt * 2 + 0] += v0 * a10 + v1 * a11;
                gacc[mt * 2 + 0] += v0 * a20 + v1 * a21;
                facc[mt * 2 + 1] += v2 * a10 + v3 * a11;
                gacc[mt * 2 + 1] += v2 * a20 + v3 * a21;
            }
            float vv[4] = {v0, v1, v2, v3};
            #pragma unroll
            for (int j = 0; j < 4; j++) {
                float u = vv[j];
                if (epi >= 1) u = (u >= 0.f) ? u : expm1f(u);
                if (epi == 2) u = (u >= 0.f) ? u : expm1f(u);
                vv[j] = u;
            }
            *(__half2*)&Cb[(long)r * ldc + c] = __floats2half2_rn(vv[0], vv[1]);
            *(__half2*)&Cb[(long)(r + 8) * ldc + c] = __floats2half2_rn(vv[2], vv[3]);
        }
    }
    if (fgEnable) {
        #pragma unroll
        for (int idx = 0; idx < 4; idx++) {
            facc[idx] += __shfl_xor_sync(0xffffffffu, facc[idx], 1);
            facc[idx] += __shfl_xor_sync(0xffffffffu, facc[idx], 2);
            gacc[idx] += __shfl_xor_sync(0xffffffffu, gacc[idx], 1);
            gacc[idx] += __shfl_xor_sync(0xffffffffu, gacc[idx], 2);
        }
        if (q == 0) {
            #pragma unroll
            for (int mt = 0; mt < 2; mt++) {
                #pragma unroll
                for (int s = 0; s < 2; s++) {
                    int row = row0 + wm * 32 + mt * 16 + g + s * 8;
                    long w = (long)b * NN + row;
                    atomicAdd(&fOut[w], facc[mt * 2 + s]);
                    atomicAdd(&gOut[w], gacc[mt * 2 + s]);
                }
            }
        }
    }
}

// ---------------- sparse softmax over neighbor lists -> fp16 P ----------------
__global__ void softmax_sparse_kernel(const float* __restrict__ f, const float* __restrict__ g,
                                      const int* __restrict__ nnz, const int* __restrict__ cols,
                                      __half* __restrict__ Pc, int totalRows) {
    int w = (int)(((long)blockIdx.x * blockDim.x + threadIdx.x) >> 5);
    int lane = threadIdx.x & 31;
    if (w >= totalRows) return;
    int b = w >> 9;
    int i = w & 511;
    float fi = f[w];
    const float* gb = g + (long)b * NN;
    int n = nnz[i];
    const int* crow = cols + i * MAXN;
    int nc = (n + 31) >> 5;

    float e[4];
    float mx = -INFINITY;
    for (int c = 0; c < nc; c++) {
        int k = c * 32 + lane;
        float v = -INFINITY;
        if (k < n) {
            float xv = fi + gb[crow[k]];
            v = (xv >= 0.f) ? xv : 0.2f * xv;
        }
        e[c] = v;
        mx = fmaxf(mx, v);
    }
    #pragma unroll
    for (int o = 16; o > 0; o >>= 1) mx = fmaxf(mx, __shfl_xor_sync(0xffffffffu, mx, o));

    float s = 0.f;
    for (int c = 0; c < nc; c++) {
        float ev = (e[c] > -1e30f) ? __expf(e[c] - mx) : 0.f;
        e[c] = ev; s += ev;
    }
    #pragma unroll
    for (int o = 16; o > 0; o >>= 1) s += __shfl_xor_sync(0xffffffffu, s, o);
    float inv = 1.0f / s;

    __half* prow = Pc + (long)w * MAXN;
    for (int c = 0; c < nc; c++) {
        int k = c * 32 + lane;
        if (k < n) prow[k] = __float2half_rn(e[c] * inv);
    }
}

// ---------------- sparse attention apply; SCH=64, fp16 smem staging, fp16 P ----------------
__global__ __launch_bounds__(256)
void spmm_kernel(const __half* __restrict__ Pc, const __half* __restrict__ Wh,
                 const int* __restrict__ nnz, const int* __restrict__ cols,
                 __half* __restrict__ Chi,
                 float* __restrict__ Cf, int writeF,
                 long whStride, long cOuter, int cDiv, long cInner, int ldc, int epi) {
    extern __shared__ __half2 WhS2[];  // [NN][SCH/2] half2
    int b = blockIdx.y;
    int c0 = blockIdx.x * SCH;
    const __half* Whb = Wh + (long)b * whStride;
    long cOff = (long)(b / cDiv) * cOuter + (long)(b % cDiv) * cInner;

    // stage fp16 Wh rows (lossless copy): 512*64 halves = 4096 uint4
    for (int idx = threadIdx.x; idx < NN * (SCH / 8); idx += 256) {
        int row = idx >> 3;
        int col8 = (idx & 7) << 3;
        uint4 v = *(const uint4*)(Whb + (long)row * FF + c0 + col8);
        *(uint4*)&WhS2[row * (SCH / 2) + (col8 >> 1)] = v;
    }
    __syncthreads();

    int warp = threadIdx.x >> 5;
    int lane = threadIdx.x & 31;
    for (int i = warp; i < NN; i += 8) {
        int n = nnz[i];
        const int* crow = cols + i * MAXN;
        const __half* prow = Pc + ((long)b * NN + i) * MAXN;
        // even/odd-k accumulator split, 2 cols per lane
        float e0 = 0.f, e1 = 0.f, o0 = 0.f, o1 = 0.f;
        int k = 0;
        for (; k + 2 <= n; k += 2) {
            int j0 = crow[k], j1 = crow[k + 1];
            float w0 = __half2float(prow[k]);
            float w1 = __half2float(prow[k + 1]);
            float2 v0 = __half22float2(WhS2[j0 * (SCH / 2) + lane]);
            float2 v1 = __half22float2(WhS2[j1 * (SCH / 2) + lane]);
            e0 += w0 * v0.x; e1 += w0 * v0.y;
            o0 += w1 * v1.x; o1 += w1 * v1.y;
        }
        if (k < n) {
            float w0 = __half2float(prow[k]);
            float2 v0 = __half22float2(WhS2[crow[k] * (SCH / 2) + lane]);
            e0 += w0 * v0.x; e1 += w0 * v0.y;
        }
        float ax = e0 + o0, ay = e1 + o1;
        if (epi >= 1) { ax = (ax >= 0.f) ? ax : expm1f(ax); ay = (ay >= 0.f) ? ay : expm1f(ay); }
        if (epi == 2) { ax = (ax >= 0.f) ? ax : expm1f(ax); ay = (ay >= 0.f) ? ay : expm1f(ay); }
        long o = cOff + (long)i * ldc + c0 + 2 * lane;
        *(__half2*)&Chi[o] = __floats2half2_rn(ax, ay);
        if (writeF) *(float2*)&Cf[o] = make_float2(ax, ay);
    }
}

// ---------------- final pool ----------------
__global__ void pool_kernel(const float* __restrict__ x, const float* __restrict__ Wo,
                            const float* __restrict__ bo, float* __restrict__ out) {
    int t = blockIdx.x;
    int f = threadIdx.x;
    __shared__ float m[FF];
    const float* xt = x + (long)t * NN * FF;
    float s = 0.f;
    for (int n = 0; n < NN; n++) s += xt[n * FF + f];
    m[f] = s * (1.0f / NN);
    __syncthreads();
    float o = bo[f];
    for (int k = 0; k < FF; k++) o += m[k] * Wo[k * FF + f];
    out[t * FF + f] = o;
}

// ---------------- host orchestration ----------------
extern "C" void kernel_launch(void* const* d_in, const int* in_sizes, int n_in,
                              void* d_out, int out_size) {
    const float* pose    = (const float*)d_in[0];
    const int*   adj     = (const int*)  d_in[1];
    const float* Wp      = (const float*)d_in[2];
    const float* bp      = (const float*)d_in[3];
    const float* W_heads = (const float*)d_in[4];
    const float* a_heads = (const float*)d_in[5];
    const float* W_out   = (const float*)d_in[6];
    const float* a_out   = (const float*)d_in[7];
    const float* Wo      = (const float*)d_in[8];
    const float* bo      = (const float*)d_in[9];
    float* out = (float*)d_out;

    float *x, *fb, *gb;
    __half *Whh, *xh, *xch, *Wth, *Woth, *P;
    int *nnz, *colsArr;
    cudaGetSymbolAddress((void**)&x,    g_x);
    cudaGetSymbolAddress((void**)&Whh,  g_Whh);
    cudaGetSymbolAddress((void**)&xh,   g_xh);
    cudaGetSymbolAddress((void**)&xch,  g_xch);
    cudaGetSymbolAddress((void**)&Wth,  g_Wth);
    cudaGetSymbolAddress((void**)&Woth, g_Woth);
    cudaGetSymbolAddress((void**)&fb,   g_f);
    cudaGetSymbolAddress((void**)&gb,   g_g);
    cudaGetSymbolAddress((void**)&P,    g_P);
    cudaGetSymbolAddress((void**)&nnz,  g_nnz);
    cudaGetSymbolAddress((void**)&colsArr, g_cols);

    static bool attrSet = false;
    if (!attrSet) {
        cudaFuncSetAttribute(spmm_kernel,
                             cudaFuncAttributeMaxDynamicSharedMemorySize, NN * SCH * 2);
        cudaFuncSetAttribute(gemm_tc,
                             cudaFuncAttributeMaxDynamicSharedMemorySize, GEMM_SMEM);
        attrSet = true;
    }

    adjlist_kernel<<<NN, 256>>>(adj, nnz, colsArr);

    {
        dim3 blk(32, 8);
        dim3 gh(FF / 32, FF / 32, LL * HH);
        wsplit_kernel<<<gh, blk>>>(W_heads, Wth, FF, FF);
        dim3 go(FF / 32, (HH * FF) / 32, LL);
        wsplit_kernel<<<go, blk>>>(W_out, Woth, HH * FF, FF);
    }

    {
        long total = (long)T_FR * NN * FF;
        input_proj_kernel<<<(unsigned)((total + 255) / 256), 256>>>(pose, Wp, bp, xh);
    }

    for (int l = 0; l < LL; l++) {
        const __half* Wlh = Wth  + (long)l * HH * FF * FF;
        const __half* Woh = Woth + (long)l * FF * HH * FF;
        const float* al  = a_heads + (long)l * HH * 2 * FF;
        const float* aol = a_out   + (long)l * 2 * FF;

        // 2a. Wh(fp16) = x @ W_heads  (fused f/g)
        zero_fg_kernel<<<(T_FR * HH * NN + 255) / 256, 256>>>(fb, gb, T_FR * HH * NN);
        {
            dim3 grid(FF / 64, NN / 128, T_FR * HH);
            gemm_tc<<<grid, 256, GEMM_SMEM>>>(xh, Wlh, Whh,
                FF, FF, FF, FF,
                (long)NN * FF, HH,
                (long)FF * FF, HH,
                (long)NN * FF, 1, 0,
                0, fb, gb, al, HH, 1);
        }
        // 2c. sparse softmax -> compact fp16 P
        {
            int rows = T_FR * HH * NN;
            softmax_sparse_kernel<<<(rows * 32 + 255) / 256, 256>>>(fb, gb, nnz, colsArr, P, rows);
        }
        // 2d. xcat = elu(P @ Wh) -> fp16  (SCH=64)
        {
            dim3 grid(FF / SCH, T_FR * HH);
            spmm_kernel<<<grid, 256, NN * SCH * 2>>>(P, Whh, nnz, colsArr,
                xch, (float*)0, 0,
                (long)NN * FF,
                (long)NN * HH * FF, HH, FF, HH * FF, 1);
        }
        // 2e. Whout(fp16) = xcat @ W_out  (K=2048, fused f/g)
        zero_fg_kernel<<<(T_FR * NN + 255) / 256, 256>>>(fb, gb, T_FR * NN);
        {
            dim3 grid(FF / 64, NN / 128, T_FR);
            gemm_tc<<<grid, 256, GEMM_SMEM>>>(xch, Woh, Whh,
                HH * FF, HH * FF, HH * FF, FF,
                (long)NN * HH * FF, 1,
                0, 1,
                (long)NN * FF, 1, 0,
                0, fb, gb, aol, 1, 1);
        }
        // 2g. sparse softmax -> compact fp16 P
        {
            int rows = T_FR * NN;
            softmax_sparse_kernel<<<(rows * 32 + 255) / 256, 256>>>(fb, gb, nnz, colsArr, P, rows);
        }
        // 2h. x = elu(elu(P @ Whout)) -> fp16 (+ fp32 last layer)
        {
            dim3 grid(FF / SCH, T_FR);
            spmm_kernel<<<grid, 256, NN * SCH * 2>>>(P, Whh, nnz, colsArr,
                xh, x, (l == LL - 1) ? 1 : 0,
                (long)NN * FF,
                (long)NN * FF, 1, 0, FF, 2);
        }
    }

    pool_kernel<<<T_FR, 256>>>(x, Wo, bo, out);
}